// round 6
// baseline (speedup 1.0000x reference)
#include <cuda_runtime.h>
#include <math.h>

// ---------------- problem constants ----------------
#define NB   8
#define NC   64
#define NH   48
#define NW   48
#define NQ   8192
#define BQ   (NB * NQ)        // 65536 queries
#define NROWS (4 * BQ)        // 262144 MLP rows (4 shifts)
#define KIN  600              // 596 padded to 600 (BK=8 multiple, float4 friendly)
#define KREAL 596
#define HID  256
#define OUTD 27

// ---------------- scratch (device globals: allocation-free rule) ----------------
__device__ float g_X  [(size_t)NROWS * KIN];   // ~629 MB
__device__ float g_H1 [(size_t)NROWS * HID];   // ~268 MB
__device__ float g_H2 [(size_t)NROWS * HID];   // ~268 MB
__device__ float g_area[NROWS];
__device__ float g_W0p[KIN * HID];             // zero-padded copy of w0

// ---------------- pad w0 into [600][256] ----------------
__global__ void pad_w0(const float* __restrict__ w0)
{
    int idx = blockIdx.x * 256 + threadIdx.x;   // 600*256 = 153600
    if (idx >= KIN * HID) return;
    int k = idx >> 8;                            // row (k-dim)
    g_W0p[idx] = (k < KREAL) ? w0[idx] : 0.0f;   // identical row-major layout for k<596
}

// ---------------- gather/build input rows + areas (one warp per row) ----------------
__global__ void build_x(const float* __restrict__ feat,
                        const float* __restrict__ coord,
                        const float* __restrict__ cell)
{
    int gw   = (blockIdx.x * blockDim.x + threadIdx.x) >> 5;
    int lane = threadIdx.x & 31;
    if (gw >= NROWS) return;

    const int s  = gw >> 16;          // shift index 0..3  (vx = s>>1 ? +1:-1, vy = s&1 ? +1:-1)
    const int bq = gw & (BQ - 1);
    const int b  = bq >> 13;          // / 8192

    const float* cp = coord + (size_t)bq * 18;

    // constants folded in double precision, then cast — matches JAX exactly
    const float SP  = (float)( 1.0 / 48.0 + 1e-6);
    const float SN  = (float)(-1.0 / 48.0 + 1e-6);
    const float CLO = (float)(-1.0 + 1e-6);
    const float CHI = (float)( 1.0 - 1e-6);

    float cx = cp[8] + ((s & 2) ? SP : SN);
    float cy = cp[9] + ((s & 1) ? SP : SN);
    cx = fminf(fmaxf(cx, CLO), CHI);
    cy = fminf(fmaxf(cy, CLO), CHI);

    // jnp.round == round-half-to-even == rintf
    int row = (int)rintf((cx + 1.0f) * 24.0f - 0.5f);
    int col = (int)rintf((cy + 1.0f) * 24.0f - 0.5f);
    row = min(max(row, 0), NH - 1);
    col = min(max(col, 0), NW - 1);

    float qcr = (float)(2 * row + 1) / 48.0f - 1.0f;
    float qcc = (float)(2 * col + 1) / 48.0f - 1.0f;

    float*       xrow = g_X + (size_t)gw * KIN;
    const float* fb   = feat + (size_t)b * (NC * NH * NW);

    // 576 feature values: x[c*9 + k] = feat[b, c, row + k/3 - 1, col + k%3 - 1] (zero-padded)
    #pragma unroll
    for (int t = 0; t < 18; t++) {
        int idx = lane + 32 * t;                 // 0..575 exactly
        int c = idx / 9;
        int k = idx - 9 * c;
        int h = row + k / 3 - 1;
        int w = col + (k % 3) - 1;
        float v = 0.0f;
        if ((unsigned)h < 48u && (unsigned)w < 48u)
            v = fb[((size_t)c * 48 + (unsigned)h) * 48 + (unsigned)w];
        xrow[idx] = v;
    }

    // tail: 18 rel values, 2 cell values, 4 zero pads
    if (lane < 24) {
        float v;
        if (lane < 18) {
            int   d  = lane & 1;
            float cv = cp[lane];
            v = d ? (cv - qcc) : (cv - qcr) * 2304.0f;   // rel_scale = (H*W, 1)
        } else if (lane < 20) {
            v = cell[(size_t)bq * 2 + (lane - 18)] * 48.0f;
        } else {
            v = 0.0f;
        }
        xrow[576 + lane] = v;
    }

    if (lane == 0) {
        float ax = (cp[0] - qcr) * 2304.0f;
        float ay = (cp[1] - qcc);
        g_area[gw] = fabsf(ax * ay) + 1e-9f;
    }
}

// ---------------- fp32 SGEMM 128x128x8, 8x8 per thread, bias + ReLU ----------------
// A/C selected at compile time from device globals (no symbol-address calls needed).
// AID: 0=g_X(lda=600), 1=g_H1, 2=g_H2   CID: 1=g_H1, 2=g_H2   USE_W0P: B = g_W0p
template<int AID, int CID, bool USE_W0P, bool RELU>
__global__ void __launch_bounds__(256)
sgemm_bias(const float* __restrict__ Bin, const float* __restrict__ bias)
{
    const float* A  = (AID == 0) ? g_X : ((AID == 1) ? g_H1 : g_H2);
    float*       C  = (CID == 1) ? g_H1 : g_H2;
    const float* Bm = USE_W0P ? g_W0p : Bin;
    const int lda = (AID == 0) ? KIN : HID;
    const int K   = lda;                 // K == lda for both cases here

    __shared__ float As[8][128];
    __shared__ float Bs[8][128];

    const int tid = threadIdx.x;
    const int bx = blockIdx.x, by = blockIdx.y;
    const int tx = tid & 15, ty = tid >> 4;

    const int arow = tid >> 1,  acol = (tid & 1) << 2;   // A tile: 128 rows x 8 k
    const int brow = tid >> 5,  bcol = (tid & 31) << 2;  // B tile:   8 k x 128 n

    const float* Ap = A  + (size_t)(by * 128 + arow) * lda + acol;
    const float* Bp = Bm + (size_t)brow * HID + bx * 128 + bcol;

    float acc[8][8];
    #pragma unroll
    for (int i = 0; i < 8; i++)
        #pragma unroll
        for (int j = 0; j < 8; j++) acc[i][j] = 0.0f;

    for (int k0 = 0; k0 < K; k0 += 8) {
        float4 av = *(const float4*)(Ap + k0);
        float4 bv = *(const float4*)(Bp + (size_t)k0 * HID);
        As[acol + 0][arow] = av.x;
        As[acol + 1][arow] = av.y;
        As[acol + 2][arow] = av.z;
        As[acol + 3][arow] = av.w;
        *(float4*)&Bs[brow][bcol] = bv;
        __syncthreads();

        #pragma unroll
        for (int k = 0; k < 8; k++) {
            float a[8], bfr[8];
            *(float4*)(a)       = *(const float4*)&As[k][ty * 4];
            *(float4*)(a + 4)   = *(const float4*)&As[k][64 + ty * 4];
            *(float4*)(bfr)     = *(const float4*)&Bs[k][tx * 4];
            *(float4*)(bfr + 4) = *(const float4*)&Bs[k][64 + tx * 4];
            #pragma unroll
            for (int i = 0; i < 8; i++)
                #pragma unroll
                for (int j = 0; j < 8; j++)
                    acc[i][j] += a[i] * bfr[j];
        }
        __syncthreads();
    }

    #pragma unroll
    for (int i = 0; i < 8; i++) {
        int r = by * 128 + ((i < 4) ? (ty * 4 + i) : (64 + ty * 4 + i - 4));
        #pragma unroll
        for (int j = 0; j < 8; j++) {
            int c = bx * 128 + ((j < 4) ? (tx * 4 + j) : (64 + tx * 4 + j - 4));
            float v = acc[i][j] + bias[c];
            if (RELU) v = fmaxf(v, 0.0f);
            C[(size_t)r * HID + c] = v;
        }
    }
}

// ---------------- blend hidden states across the 4 shifts (last layer is linear) ----
// reference swaps areas: pred[s] is weighted by area[3-s] / tot
__global__ void combine_h()
{
    size_t idx = (size_t)blockIdx.x * 256 + threadIdx.x;   // BQ*HID total
    int bq = (int)(idx >> 8);
    float a0 = g_area[bq];
    float a1 = g_area[BQ + bq];
    float a2 = g_area[2 * BQ + bq];
    float a3 = g_area[3 * BQ + bq];
    float inv = 1.0f / (a0 + a1 + a2 + a3);
    const size_t CH = (size_t)BQ * HID;
    float v = g_H2[idx] * a3 + g_H2[CH + idx] * a2
            + g_H2[2 * CH + idx] * a1 + g_H2[3 * CH + idx] * a0;
    g_H1[idx] = v * inv;   // store blended h4 in first BQ rows of g_H1
}

// ---------------- final 256 -> 27 GEMM + bias ----------------
__global__ void __launch_bounds__(256) final_gemm(const float* __restrict__ w4,
                                                  const float* __restrict__ b4,
                                                  float* __restrict__ out)
{
    __shared__ float W4s[HID * OUTD];   // 27648 B
    __shared__ float Hs[16][HID];       // 16384 B

    int tid = threadIdx.x;
    for (int i = tid; i < HID * OUTD; i += 256) W4s[i] = w4[i];
    size_t row0 = (size_t)blockIdx.x * 16;
    for (int i = tid; i < 16 * HID; i += 256)
        Hs[i >> 8][i & 255] = g_H1[(row0 + (size_t)(i >> 8)) * HID + (i & 255)];
    __syncthreads();

    for (int idx = tid; idx < 16 * OUTD; idx += 256) {
        int r = idx / OUTD, o = idx - r * OUTD;
        float s = 0.0f;
        #pragma unroll 8
        for (int k = 0; k < HID; k++) s += Hs[r][k] * W4s[k * OUTD + o];
        out[(row0 + r) * OUTD + o] = s + b4[o];
    }
}

// ---------------- launch ----------------
extern "C" void kernel_launch(void* const* d_in, const int* in_sizes, int n_in,
                              void* d_out, int out_size)
{
    const float* feat  = (const float*)d_in[0];
    const float* coord = (const float*)d_in[1];
    const float* cell  = (const float*)d_in[2];
    const float* w0 = (const float*)d_in[3];
    const float* b0 = (const float*)d_in[4];
    const float* w1 = (const float*)d_in[5];
    const float* b1 = (const float*)d_in[6];
    const float* w2 = (const float*)d_in[7];
    const float* b2 = (const float*)d_in[8];
    const float* w3 = (const float*)d_in[9];
    const float* b3 = (const float*)d_in[10];
    const float* w4 = (const float*)d_in[11];
    const float* b4 = (const float*)d_in[12];
    float* out = (float*)d_out;

    pad_w0 <<<600, 256>>>(w0);
    build_x<<<NROWS / 8, 256>>>(feat, coord, cell);

    dim3 g(HID / 128, NROWS / 128);   // (2, 2048)
    sgemm_bias<0, 1, true,  true><<<g, 256>>>(nullptr, b0);  // X  @ W0p -> H1
    sgemm_bias<1, 2, false, true><<<g, 256>>>(w1, b1);       // H1 @ w1  -> H2
    sgemm_bias<2, 1, false, true><<<g, 256>>>(w2, b2);       // H2 @ w2  -> H1
    sgemm_bias<1, 2, false, true><<<g, 256>>>(w3, b3);       // H1 @ w3  -> H2

    combine_h <<<BQ, 256>>>();                               // H2(4 shifts) -> H1[0:BQ]
    final_gemm<<<BQ / 16, 256>>>(w4, b4, out);               // H1 @ w4 + b4 -> out
}

// round 8
// speedup vs baseline: 1.6704x; 1.6704x over previous
#include <cuda_runtime.h>
#include <cuda_bf16.h>
#include <math.h>
#include <cstdint>

// ---------------- problem constants ----------------
#define NBATCH 8
#define NCHAN  64
#define NH     48
#define NW     48
#define NQ     8192
#define BQ     (NBATCH * NQ)      // 65536 queries
#define NROWS  (4 * BQ)           // 262144 MLP rows (4 shifts)
#define KIN    608                // 596 padded to 608 (19 chunks of 32)
#define KREAL  596
#define HID    256
#define OUTD   27

typedef __nv_bfloat16 bf16;

// ---------------- scratch (device globals: allocation-free rule) ----------------
__device__ bf16  g_Xh [(size_t)NROWS * KIN];   // ~319 MB
__device__ bf16  g_Xl [(size_t)NROWS * KIN];
__device__ bf16  g_H1h[(size_t)NROWS * HID];   // ~134 MB each
__device__ bf16  g_H1l[(size_t)NROWS * HID];
__device__ bf16  g_H2h[(size_t)NROWS * HID];
__device__ bf16  g_H2l[(size_t)NROWS * HID];
__device__ float g_Hc [(size_t)BQ * HID];      // blended hidden, fp32
__device__ float g_area[NROWS];
__device__ bf16  g_W0h[HID * KIN];             // weight^T planes: [n][k]
__device__ bf16  g_W0l[HID * KIN];
__device__ bf16  g_W1h[HID * HID];
__device__ bf16  g_W1l[HID * HID];
__device__ bf16  g_W2h[HID * HID];
__device__ bf16  g_W2l[HID * HID];
__device__ bf16  g_W3h[HID * HID];
__device__ bf16  g_W3l[HID * HID];

// ---------------- PTX helpers (all sm_80+ features, valid on base sm_103) ------
__device__ __forceinline__ uint32_t smem_u32(const void* p) {
    uint32_t a;
    asm("{ .reg .u64 t; cvta.to.shared.u64 t, %1; cvt.u32.u64 %0, t; }" : "=r"(a) : "l"(p));
    return a;
}
__device__ __forceinline__ void cpa16(uint32_t s, const void* g) {
    asm volatile("cp.async.cg.shared.global [%0], [%1], 16;" :: "r"(s), "l"(g));
}
#define CP_COMMIT() asm volatile("cp.async.commit_group;" ::: "memory")
template<int N>
__device__ __forceinline__ void cp_wait() {
    asm volatile("cp.async.wait_group %0;" :: "n"(N) : "memory");
}
__device__ __forceinline__ void ldsm4(uint32_t (&r)[4], uint32_t addr) {
    asm volatile("ldmatrix.sync.aligned.m8n8.x4.shared.b16 {%0,%1,%2,%3}, [%4];"
        : "=r"(r[0]), "=r"(r[1]), "=r"(r[2]), "=r"(r[3]) : "r"(addr));
}
__device__ __forceinline__ void mma16816(float (&c)[4], const uint32_t (&a)[4],
                                         uint32_t b0, uint32_t b1) {
    asm volatile("mma.sync.aligned.m16n8k16.row.col.f32.bf16.bf16.f32 "
        "{%0,%1,%2,%3}, {%4,%5,%6,%7}, {%8,%9}, {%0,%1,%2,%3};"
        : "+f"(c[0]), "+f"(c[1]), "+f"(c[2]), "+f"(c[3])
        : "r"(a[0]), "r"(a[1]), "r"(a[2]), "r"(a[3]), "r"(b0), "r"(b1));
}
__device__ __forceinline__ void split_bf16(float v, bf16& h, bf16& l) {
    h = __float2bfloat16(v);
    l = __float2bfloat16(v - __bfloat162float(h));
}

// ---------------- smem layout for the GEMM ----------------
// row stride 40 bf16 = 80 B: bank-group starts 20r mod 32 = {0,20,8,28,16,4,24,12}
// for 8 consecutive rows -> all ldmatrix 8-row reads conflict-free.
#define LDSR   40
#define OA     0
#define OAL    10240
#define OB     20480
#define OBL    30720
#define STAGE  40960
#define SMEM_BYTES (512 + 2 * STAGE)   // bias(512) + 2 stages = 82432

// ---------------- weight prep: transpose + hi/lo split ----------------
__global__ void prep_weights(const float* __restrict__ w0, const float* __restrict__ w1,
                             const float* __restrict__ w2, const float* __restrict__ w3)
{
    int idx = blockIdx.x * 256 + threadIdx.x;      // grid 608 -> 155648
    if (idx < HID * KIN) {
        int n = idx / KIN, k = idx - n * KIN;
        float v = (k < KREAL) ? w0[k * HID + n] : 0.0f;
        split_bf16(v, g_W0h[idx], g_W0l[idx]);
    }
    if (idx < HID * HID) {
        int n = idx >> 8, k = idx & 255;
        split_bf16(w1[k * HID + n], g_W1h[idx], g_W1l[idx]);
        split_bf16(w2[k * HID + n], g_W2h[idx], g_W2l[idx]);
        split_bf16(w3[k * HID + n], g_W3h[idx], g_W3l[idx]);
    }
}

// ---------------- gather/build input rows (hi/lo planes) + areas ----------------
__global__ void build_x(const float* __restrict__ feat,
                        const float* __restrict__ coord,
                        const float* __restrict__ cell)
{
    int gw   = (blockIdx.x * blockDim.x + threadIdx.x) >> 5;
    int lane = threadIdx.x & 31;
    if (gw >= NROWS) return;

    const int s  = gw >> 16;
    const int bq = gw & (BQ - 1);
    const int b  = bq >> 13;

    const float* cp = coord + (size_t)bq * 18;

    const float SP  = (float)( 1.0 / 48.0 + 1e-6);
    const float SN  = (float)(-1.0 / 48.0 + 1e-6);
    const float CLO = (float)(-1.0 + 1e-6);
    const float CHI = (float)( 1.0 - 1e-6);

    float cx = cp[8] + ((s & 2) ? SP : SN);
    float cy = cp[9] + ((s & 1) ? SP : SN);
    cx = fminf(fmaxf(cx, CLO), CHI);
    cy = fminf(fmaxf(cy, CLO), CHI);

    int row = (int)rintf((cx + 1.0f) * 24.0f - 0.5f);
    int col = (int)rintf((cy + 1.0f) * 24.0f - 0.5f);
    row = min(max(row, 0), NH - 1);
    col = min(max(col, 0), NW - 1);

    float qcr = (float)(2 * row + 1) / 48.0f - 1.0f;
    float qcc = (float)(2 * col + 1) / 48.0f - 1.0f;

    const size_t base = (size_t)gw * KIN;
    const float* fb   = feat + (size_t)b * (NCHAN * NH * NW);

    #pragma unroll
    for (int t = 0; t < 18; t++) {
        int idx = lane + 32 * t;                 // 0..575
        int c = idx / 9;
        int k = idx - 9 * c;
        int h = row + k / 3 - 1;
        int w = col + (k % 3) - 1;
        float v = 0.0f;
        if ((unsigned)h < 48u && (unsigned)w < 48u)
            v = fb[((size_t)c * 48 + (unsigned)h) * 48 + (unsigned)w];
        split_bf16(v, g_Xh[base + idx], g_Xl[base + idx]);
    }

    {
        float v;
        if (lane < 18) {
            int   d  = lane & 1;
            float cv = cp[lane];
            v = d ? (cv - qcc) : (cv - qcr) * 2304.0f;
        } else if (lane < 20) {
            v = cell[(size_t)bq * 2 + (lane - 18)] * 48.0f;
        } else {
            v = 0.0f;
        }
        split_bf16(v, g_Xh[base + 576 + lane], g_Xl[base + 576 + lane]);
    }

    if (lane == 0) {
        float ax = (cp[0] - qcr) * 2304.0f;
        float ay = (cp[1] - qcc);
        g_area[gw] = fabsf(ax * ay) + 1e-9f;
    }
}

// ---------------- bf16x3 HMMA GEMM: C = relu(A @ W^T + bias), hi/lo planes ------
// CTA 128(M) x 128(N), 256 threads = 8 warps (2 M x 4 N), warp tile 64x32.
// K chunks of 32, double-buffered cp.async.
template<int AID, int CID, int KPAD, int NCHUNK, int WID>
__global__ void __launch_bounds__(256) gemm_bf16x3(const float* __restrict__ bias)
{
    extern __shared__ char smem[];
    const bf16* Aph = (AID == 0) ? g_Xh : ((AID == 1) ? g_H1h : g_H2h);
    const bf16* Apl = (AID == 0) ? g_Xl : ((AID == 1) ? g_H1l : g_H2l);
    bf16*       Cph = (CID == 1) ? g_H1h : g_H2h;
    bf16*       Cpl = (CID == 1) ? g_H1l : g_H2l;
    const bf16* Wph = (WID == 0) ? g_W0h : ((WID == 1) ? g_W1h : ((WID == 2) ? g_W2h : g_W3h));
    const bf16* Wpl = (WID == 0) ? g_W0l : ((WID == 1) ? g_W1l : ((WID == 2) ? g_W2l : g_W3l));

    const int tid  = threadIdx.x;
    const int lane = tid & 31;
    const int wid  = tid >> 5;
    const int wm   = wid & 1;        // M half (64 rows)
    const int wn   = wid >> 1;       // N quarter (32 cols)
    const int bx   = blockIdx.x;
    const size_t row0 = (size_t)blockIdx.y * 128;

    float* bias_s = (float*)smem;
    if (tid < 128) bias_s[tid] = bias[bx * 128 + tid];

    const uint32_t sb  = smem_u32(smem);
    const uint32_t ST0 = sb + 512;

    // per-lane ldmatrix row-address offsets (bytes within a plane)
    uint32_t aoff[4], boff[2];
    #pragma unroll
    for (int i = 0; i < 4; i++)
        aoff[i] = (uint32_t)((wm * 64 + i * 16 + (lane & 15)) * (LDSR * 2) + ((lane >> 4) << 4));
    #pragma unroll
    for (int j = 0; j < 2; j++)
        boff[j] = (uint32_t)((wn * 32 + j * 16 + (lane & 7) + ((lane >> 4) << 3)) * (LDSR * 2)
                             + (((lane >> 3) & 1) << 4));

    // cp.async assignment: 2 threads per row, 2x16B segments each, per plane
    const int cr = tid >> 1;
    const int sg = (tid & 1) << 1;

    auto load_chunk = [&](int c, int st) {
        uint32_t base = ST0 + st * STAGE;
        uint32_t so   = (uint32_t)(cr * (LDSR * 2) + (sg << 4));
        const bf16* ga  = Aph + (row0 + cr) * KPAD + c * 32 + sg * 8;
        const bf16* gal = Apl + (row0 + cr) * KPAD + c * 32 + sg * 8;
        const bf16* gb  = Wph + (size_t)(bx * 128 + cr) * KPAD + c * 32 + sg * 8;
        const bf16* gbl = Wpl + (size_t)(bx * 128 + cr) * KPAD + c * 32 + sg * 8;
        cpa16(base + OA  + so,      ga);
        cpa16(base + OA  + so + 16, ga + 8);
        cpa16(base + OAL + so,      gal);
        cpa16(base + OAL + so + 16, gal + 8);
        cpa16(base + OB  + so,      gb);
        cpa16(base + OB  + so + 16, gb + 8);
        cpa16(base + OBL + so,      gbl);
        cpa16(base + OBL + so + 16, gbl + 8);
    };

    float acc[4][4][4];
    #pragma unroll
    for (int i = 0; i < 4; i++)
        #pragma unroll
        for (int j = 0; j < 4; j++)
            #pragma unroll
            for (int r = 0; r < 4; r++) acc[i][j][r] = 0.0f;

    load_chunk(0, 0);
    CP_COMMIT();

    for (int c = 0; c < NCHUNK; c++) {
        const int st = c & 1;
        if (c + 1 < NCHUNK) {
            load_chunk(c + 1, st ^ 1);
            CP_COMMIT();
            cp_wait<1>();
        } else {
            cp_wait<0>();
        }
        __syncthreads();

        uint32_t base = ST0 + st * STAGE;
        #pragma unroll
        for (int kk = 0; kk < 2; kk++) {
            const uint32_t ko = (uint32_t)(kk << 5);   // 16 bf16 = 32 bytes
            uint32_t ah[4][4], al[4][4], bh[2][4], bl[2][4];
            #pragma unroll
            for (int i = 0; i < 4; i++) ldsm4(ah[i], base + OA  + aoff[i] + ko);
            #pragma unroll
            for (int i = 0; i < 4; i++) ldsm4(al[i], base + OAL + aoff[i] + ko);
            #pragma unroll
            for (int j = 0; j < 2; j++) ldsm4(bh[j], base + OB  + boff[j] + ko);
            #pragma unroll
            for (int j = 0; j < 2; j++) ldsm4(bl[j], base + OBL + boff[j] + ko);

            #pragma unroll
            for (int i = 0; i < 4; i++)
                #pragma unroll
                for (int j = 0; j < 2; j++)
                    #pragma unroll
                    for (int h = 0; h < 2; h++) {
                        const int jj = j * 2 + h;
                        mma16816(acc[i][jj], ah[i], bh[j][2 * h], bh[j][2 * h + 1]);
                        mma16816(acc[i][jj], al[i], bh[j][2 * h], bh[j][2 * h + 1]);
                        mma16816(acc[i][jj], ah[i], bl[j][2 * h], bl[j][2 * h + 1]);
                    }
        }
        __syncthreads();
    }

    // ---- epilogue: bias + relu, split to hi/lo planes ----
    #pragma unroll
    for (int i = 0; i < 4; i++) {
        const size_t r0 = row0 + wm * 64 + i * 16 + (lane >> 2);
        #pragma unroll
        for (int jj = 0; jj < 4; jj++) {
            const int ncl = wn * 32 + jj * 8 + (lane & 3) * 2;
            const int ncg = bx * 128 + ncl;
            const float bz0 = bias_s[ncl], bz1 = bias_s[ncl + 1];
            #pragma unroll
            for (int p = 0; p < 2; p++) {          // p=0: row r0, p=1: row r0+8
                float v0 = fmaxf(acc[i][jj][2 * p + 0] + bz0, 0.0f);
                float v1 = fmaxf(acc[i][jj][2 * p + 1] + bz1, 0.0f);
                bf16 h0, l0, h1, l1;
                split_bf16(v0, h0, l0);
                split_bf16(v1, h1, l1);
                const size_t off = (r0 + p * 8) * HID + ncg;
                *(__nv_bfloat162*)(Cph + off) = __nv_bfloat162(h0, h1);
                *(__nv_bfloat162*)(Cpl + off) = __nv_bfloat162(l0, l1);
            }
        }
    }
}

// ---------------- blend hidden states across the 4 shifts (last layer linear) ----
__global__ void combine_h()
{
    size_t idx = (size_t)blockIdx.x * 256 + threadIdx.x;   // BQ*HID total
    int bq = (int)(idx >> 8);
    float a0 = g_area[bq];
    float a1 = g_area[BQ + bq];
    float a2 = g_area[2 * BQ + bq];
    float a3 = g_area[3 * BQ + bq];
    float inv = 1.0f / (a0 + a1 + a2 + a3);
    const size_t CH = (size_t)BQ * HID;
    float v0 = __bfloat162float(g_H2h[idx])          + __bfloat162float(g_H2l[idx]);
    float v1 = __bfloat162float(g_H2h[CH + idx])     + __bfloat162float(g_H2l[CH + idx]);
    float v2 = __bfloat162float(g_H2h[2 * CH + idx]) + __bfloat162float(g_H2l[2 * CH + idx]);
    float v3 = __bfloat162float(g_H2h[3 * CH + idx]) + __bfloat162float(g_H2l[3 * CH + idx]);
    g_Hc[idx] = (v0 * a3 + v1 * a2 + v2 * a1 + v3 * a0) * inv;
}

// ---------------- final 256 -> 27 GEMM + bias (fp32) ----------------
__global__ void __launch_bounds__(256) final_gemm(const float* __restrict__ w4,
                                                  const float* __restrict__ b4,
                                                  float* __restrict__ out)
{
    __shared__ float W4s[HID * OUTD];
    __shared__ float Hs[16][HID];

    int tid = threadIdx.x;
    for (int i = tid; i < HID * OUTD; i += 256) W4s[i] = w4[i];
    size_t row0 = (size_t)blockIdx.x * 16;
    for (int i = tid; i < 16 * HID; i += 256)
        Hs[i >> 8][i & 255] = g_Hc[(row0 + (size_t)(i >> 8)) * HID + (i & 255)];
    __syncthreads();

    for (int idx = tid; idx < 16 * OUTD; idx += 256) {
        int r = idx / OUTD, o = idx - r * OUTD;
        float s = 0.0f;
        #pragma unroll 8
        for (int k = 0; k < HID; k++) s += Hs[r][k] * W4s[k * OUTD + o];
        out[(row0 + r) * OUTD + o] = s + b4[o];
    }
}

// ---------------- launch ----------------
extern "C" void kernel_launch(void* const* d_in, const int* in_sizes, int n_in,
                              void* d_out, int out_size)
{
    const float* feat  = (const float*)d_in[0];
    const float* coord = (const float*)d_in[1];
    const float* cell  = (const float*)d_in[2];
    const float* w0 = (const float*)d_in[3];
    const float* b0 = (const float*)d_in[4];
    const float* w1 = (const float*)d_in[5];
    const float* b1 = (const float*)d_in[6];
    const float* w2 = (const float*)d_in[7];
    const float* b2 = (const float*)d_in[8];
    const float* w3 = (const float*)d_in[9];
    const float* b3 = (const float*)d_in[10];
    const float* w4 = (const float*)d_in[11];
    const float* b4 = (const float*)d_in[12];
    float* out = (float*)d_out;

    cudaFuncSetAttribute(gemm_bf16x3<0, 1, KIN, 19, 0>, cudaFuncAttributeMaxDynamicSharedMemorySize, SMEM_BYTES);
    cudaFuncSetAttribute(gemm_bf16x3<1, 2, HID,  8, 1>, cudaFuncAttributeMaxDynamicSharedMemorySize, SMEM_BYTES);
    cudaFuncSetAttribute(gemm_bf16x3<2, 1, HID,  8, 2>, cudaFuncAttributeMaxDynamicSharedMemorySize, SMEM_BYTES);
    cudaFuncSetAttribute(gemm_bf16x3<1, 2, HID,  8, 3>, cudaFuncAttributeMaxDynamicSharedMemorySize, SMEM_BYTES);

    prep_weights<<<KIN, 256>>>(w0, w1, w2, w3);
    build_x<<<NROWS / 8, 256>>>(feat, coord, cell);

    dim3 g(HID / 128, NROWS / 128);   // (2, 2048)
    gemm_bf16x3<0, 1, KIN, 19, 0><<<g, 256, SMEM_BYTES>>>(b0);  // X  @ W0^T -> H1
    gemm_bf16x3<1, 2, HID,  8, 1><<<g, 256, SMEM_BYTES>>>(b1);  // H1 @ W1^T -> H2
    gemm_bf16x3<2, 1, HID,  8, 2><<<g, 256, SMEM_BYTES>>>(b2);  // H2 @ W2^T -> H1
    gemm_bf16x3<1, 2, HID,  8, 3><<<g, 256, SMEM_BYTES>>>(b3);  // H1 @ W3^T -> H2

    combine_h <<<BQ, 256>>>();
    final_gemm<<<BQ / 16, 256>>>(w4, b4, out);
}

// round 9
// speedup vs baseline: 2.1892x; 1.3106x over previous
#include <cuda_runtime.h>
#include <cuda_bf16.h>
#include <math.h>
#include <cstdint>

// ---------------- problem constants ----------------
#define NBATCH 8
#define NCHAN  64
#define NH     48
#define NW     48
#define NQ     8192
#define BQ     (NBATCH * NQ)      // 65536 queries
#define NROWS  (4 * BQ)           // 262144 MLP rows (4 shifts)
#define KIN    608                // 596 padded to 608 (19 chunks of 32)
#define KREAL  596
#define HID    256
#define OUTD   27

typedef __nv_bfloat16 bf16;

// ---------------- scratch (device globals: allocation-free rule) ----------------
__device__ bf16  g_Fh [NBATCH * NH * NW * NCHAN];   // feat NHWC hi plane (2.25 MB)
__device__ bf16  g_Fl [NBATCH * NH * NW * NCHAN];   // feat NHWC lo plane
__device__ bf16  g_H1h[(size_t)NROWS * HID];        // ~134 MB each
__device__ bf16  g_H1l[(size_t)NROWS * HID];
__device__ bf16  g_H2h[(size_t)NROWS * HID];
__device__ bf16  g_H2l[(size_t)NROWS * HID];
__device__ float g_area[NROWS];
__device__ bf16  g_W0h[HID * KIN];                  // w0^T, K-permuted (k' = p*64+c)
__device__ bf16  g_W0l[HID * KIN];
__device__ bf16  g_W1h[HID * HID];
__device__ bf16  g_W1l[HID * HID];
__device__ bf16  g_W2h[HID * HID];
__device__ bf16  g_W2l[HID * HID];
__device__ bf16  g_W3h[HID * HID];
__device__ bf16  g_W3l[HID * HID];

// ---------------- PTX helpers ----------------
__device__ __forceinline__ uint32_t smem_u32(const void* p) {
    uint32_t a;
    asm("{ .reg .u64 t; cvta.to.shared.u64 t, %1; cvt.u32.u64 %0, t; }" : "=r"(a) : "l"(p));
    return a;
}
__device__ __forceinline__ void cpa16(uint32_t s, const void* g) {
    asm volatile("cp.async.cg.shared.global [%0], [%1], 16;" :: "r"(s), "l"(g));
}
// zero-fill variant: n = 16 (copy) or 0 (fill zeros)
__device__ __forceinline__ void cpa16z(uint32_t s, const void* g, uint32_t n) {
    asm volatile("cp.async.cg.shared.global [%0], [%1], 16, %2;" :: "r"(s), "l"(g), "r"(n));
}
#define CP_COMMIT() asm volatile("cp.async.commit_group;" ::: "memory")
template<int N>
__device__ __forceinline__ void cp_wait() {
    asm volatile("cp.async.wait_group %0;" :: "n"(N) : "memory");
}
__device__ __forceinline__ void ldsm4(uint32_t (&r)[4], uint32_t addr) {
    asm volatile("ldmatrix.sync.aligned.m8n8.x4.shared.b16 {%0,%1,%2,%3}, [%4];"
        : "=r"(r[0]), "=r"(r[1]), "=r"(r[2]), "=r"(r[3]) : "r"(addr));
}
__device__ __forceinline__ void mma16816(float (&c)[4], const uint32_t (&a)[4],
                                         uint32_t b0, uint32_t b1) {
    asm volatile("mma.sync.aligned.m16n8k16.row.col.f32.bf16.bf16.f32 "
        "{%0,%1,%2,%3}, {%4,%5,%6,%7}, {%8,%9}, {%0,%1,%2,%3};"
        : "+f"(c[0]), "+f"(c[1]), "+f"(c[2]), "+f"(c[3])
        : "r"(a[0]), "r"(a[1]), "r"(a[2]), "r"(a[3]), "r"(b0), "r"(b1));
}
__device__ __forceinline__ void split_bf16(float v, bf16& h, bf16& l) {
    h = __float2bfloat16(v);
    l = __float2bfloat16(v - __bfloat162float(h));
}

// ---------------- smem layout for the GEMMs ----------------
// row stride 40 bf16 = 80 B -> conflict-free ldmatrix over 8-row groups.
#define LDSR   40
#define OA     0
#define OAL    10240
#define OB     20480
#define OBL    30720
#define STAGE  40960
#define SMEM_BYTES (512 + 2 * STAGE)   // bias(512) + 2 stages = 82432

// ---------------- weight prep: transpose + hi/lo split (+ K-permute for w0) ----
__global__ void prep_weights(const float* __restrict__ w0, const float* __restrict__ w1,
                             const float* __restrict__ w2, const float* __restrict__ w3)
{
    int idx = blockIdx.x * 256 + threadIdx.x;      // grid 608 -> 155648
    if (idx < HID * KIN) {
        int n = idx / KIN, kp = idx - n * KIN;     // kp = permuted k'
        int ko;
        if (kp < 576) { int p = kp >> 6, c = kp & 63; ko = c * 9 + p; }
        else          { ko = kp; }
        float v = (kp < KREAL) ? w0[ko * HID + n] : 0.0f;
        split_bf16(v, g_W0h[idx], g_W0l[idx]);
    }
    if (idx < HID * HID) {
        int n = idx >> 8, k = idx & 255;
        split_bf16(w1[k * HID + n], g_W1h[idx], g_W1l[idx]);
        split_bf16(w2[k * HID + n], g_W2h[idx], g_W2l[idx]);
        split_bf16(w3[k * HID + n], g_W3h[idx], g_W3l[idx]);
    }
}

// ---------------- feat -> NHWC bf16 hi/lo planes ----------------
__global__ void feat_prep(const float* __restrict__ feat)
{
    int idx = blockIdx.x * 256 + threadIdx.x;      // 1179648 total
    if (idx >= NBATCH * NH * NW * NCHAN) return;
    int t = idx;
    int c = t & 63; t >>= 6;
    int w = t % 48; t /= 48;
    int h = t % 48; int b = t / 48;
    float v = feat[(((size_t)b * 64 + c) * 48 + h) * 48 + w];
    split_bf16(v, g_Fh[idx], g_Fl[idx]);
}

// ---------------- coordinate helper (shared by area + gemm0) ----------------
__device__ __forceinline__ void calc_rc(const float* cp, int s, int& row, int& col)
{
    const float SP  = (float)( 1.0 / 48.0 + 1e-6);
    const float SN  = (float)(-1.0 / 48.0 + 1e-6);
    const float CLO = (float)(-1.0 + 1e-6);
    const float CHI = (float)( 1.0 - 1e-6);
    float cx = cp[8] + ((s & 2) ? SP : SN);
    float cy = cp[9] + ((s & 1) ? SP : SN);
    cx = fminf(fmaxf(cx, CLO), CHI);
    cy = fminf(fmaxf(cy, CLO), CHI);
    row = (int)rintf((cx + 1.0f) * 24.0f - 0.5f);
    col = (int)rintf((cy + 1.0f) * 24.0f - 0.5f);
    row = min(max(row, 0), NH - 1);
    col = min(max(col, 0), NW - 1);
}

// ---------------- per-row areas ----------------
__global__ void build_area(const float* __restrict__ coord)
{
    int gw = blockIdx.x * 256 + threadIdx.x;
    if (gw >= NROWS) return;
    const int s  = gw >> 16;
    const int bq = gw & (BQ - 1);
    const float* cp = coord + (size_t)bq * 18;
    int row, col;
    calc_rc(cp, s, row, col);
    float qcr = (float)(2 * row + 1) / 48.0f - 1.0f;
    float qcc = (float)(2 * col + 1) / 48.0f - 1.0f;
    float ax = (cp[0] - qcr) * 2304.0f;
    float ay = (cp[1] - qcc);
    g_area[gw] = fabsf(ax * ay) + 1e-9f;
}

// ---------------- shared MMA inner step (3-term bf16 split, staged reg use) ----
#define MMA_CHUNK(base)                                                             \
    _Pragma("unroll")                                                               \
    for (int kk = 0; kk < 2; kk++) {                                                \
        const uint32_t ko = (uint32_t)(kk << 5);                                    \
        uint32_t ah[4][4], bh[2][4];                                                \
        _Pragma("unroll")                                                           \
        for (int i = 0; i < 4; i++) ldsm4(ah[i], (base) + OA + aoff[i] + ko);       \
        _Pragma("unroll")                                                           \
        for (int j = 0; j < 2; j++) ldsm4(bh[j], (base) + OB + boff[j] + ko);       \
        _Pragma("unroll")                                                           \
        for (int i = 0; i < 4; i++)                                                 \
            _Pragma("unroll")                                                       \
            for (int j = 0; j < 2; j++)                                             \
                _Pragma("unroll")                                                   \
                for (int h = 0; h < 2; h++)                                         \
                    mma16816(acc[i][j * 2 + h], ah[i], bh[j][2 * h], bh[j][2 * h + 1]); \
        uint32_t al[4][4];                                                          \
        _Pragma("unroll")                                                           \
        for (int i = 0; i < 4; i++) ldsm4(al[i], (base) + OAL + aoff[i] + ko);      \
        _Pragma("unroll")                                                           \
        for (int i = 0; i < 4; i++)                                                 \
            _Pragma("unroll")                                                       \
            for (int j = 0; j < 2; j++)                                             \
                _Pragma("unroll")                                                   \
                for (int h = 0; h < 2; h++)                                         \
                    mma16816(acc[i][j * 2 + h], al[i], bh[j][2 * h], bh[j][2 * h + 1]); \
        uint32_t bl[2][4];                                                          \
        _Pragma("unroll")                                                           \
        for (int j = 0; j < 2; j++) ldsm4(bl[j], (base) + OBL + boff[j] + ko);      \
        _Pragma("unroll")                                                           \
        for (int i = 0; i < 4; i++)                                                 \
            _Pragma("unroll")                                                       \
            for (int j = 0; j < 2; j++)                                             \
                _Pragma("unroll")                                                   \
                for (int h = 0; h < 2; h++)                                         \
                    mma16816(acc[i][j * 2 + h], ah[i], bl[j][2 * h], bl[j][2 * h + 1]); \
    }

#define EPILOGUE(Cph, Cpl)                                                          \
    _Pragma("unroll")                                                               \
    for (int i = 0; i < 4; i++) {                                                   \
        const size_t r0 = row0 + wm * 64 + i * 16 + (lane >> 2);                    \
        _Pragma("unroll")                                                           \
        for (int jj = 0; jj < 4; jj++) {                                            \
            const int ncl = wn * 32 + jj * 8 + (lane & 3) * 2;                      \
            const int ncg = bx * 128 + ncl;                                         \
            const float bz0 = bias_s[ncl], bz1 = bias_s[ncl + 1];                   \
            _Pragma("unroll")                                                       \
            for (int p = 0; p < 2; p++) {                                           \
                float v0 = fmaxf(acc[i][jj][2 * p + 0] + bz0, 0.0f);                \
                float v1 = fmaxf(acc[i][jj][2 * p + 1] + bz1, 0.0f);                \
                bf16 h0, l0, h1, l1;                                                \
                split_bf16(v0, h0, l0);                                             \
                split_bf16(v1, h1, l1);                                             \
                const size_t off = (r0 + p * 8) * HID + ncg;                        \
                *(__nv_bfloat162*)((Cph) + off) = __nv_bfloat162(h0, h1);           \
                *(__nv_bfloat162*)((Cpl) + off) = __nv_bfloat162(l0, l1);           \
            }                                                                       \
        }                                                                           \
    }

#define FRAG_OFFSETS()                                                              \
    uint32_t aoff[4], boff[2];                                                      \
    _Pragma("unroll")                                                               \
    for (int i = 0; i < 4; i++)                                                     \
        aoff[i] = (uint32_t)((wm * 64 + i * 16 + (lane & 15)) * (LDSR * 2)          \
                             + ((lane >> 4) << 4));                                 \
    _Pragma("unroll")                                                               \
    for (int j = 0; j < 2; j++)                                                     \
        boff[j] = (uint32_t)((wn * 32 + j * 16 + (lane & 7) + ((lane >> 4) << 3))   \
                             * (LDSR * 2) + (((lane >> 3) & 1) << 4));

// ---------------- layer 0: fused gather + bf16x3 GEMM ----------------
// A rows gathered straight from feat NHWC planes (K permuted: k' = p*64 + c).
__global__ void __launch_bounds__(256, 2)
gemm0_fused(const float* __restrict__ coord, const float* __restrict__ cell,
            const float* __restrict__ bias)
{
    extern __shared__ char smem[];
    const int tid  = threadIdx.x;
    const int lane = tid & 31;
    const int wid  = tid >> 5;
    const int wm   = wid & 1;
    const int wn   = wid >> 1;
    const int bx   = blockIdx.x;
    const size_t row0 = (size_t)blockIdx.y * 128;

    float* bias_s = (float*)smem;
    if (tid < 128) bias_s[tid] = bias[bx * 128 + tid];

    const uint32_t sb  = smem_u32(smem);
    const uint32_t ST0 = sb + 512;

    FRAG_OFFSETS();

    // per-thread gather row (2 threads per row)
    const int cr = tid >> 1;
    const int sg = (tid & 1) << 1;
    const size_t grow = row0 + cr;
    const int s  = (int)(grow >> 16);
    const int bq = (int)(grow & (BQ - 1));
    const int b  = bq >> 13;
    const float* cp = coord + (size_t)bq * 18;
    int irow, icol;
    calc_rc(cp, s, irow, icol);

    auto load_chunk = [&](int c, int ps) {
        uint32_t base = ST0 + (uint32_t)ps * STAGE;
        uint32_t so   = (uint32_t)(cr * (LDSR * 2) + (sg << 4));
        const bf16* gb  = g_W0h + (size_t)(bx * 128 + cr) * KIN + c * 32 + sg * 8;
        const bf16* gbl = g_W0l + (size_t)(bx * 128 + cr) * KIN + c * 32 + sg * 8;
        cpa16(base + OB  + so,      gb);
        cpa16(base + OB  + so + 16, gb + 8);
        cpa16(base + OBL + so,      gbl);
        cpa16(base + OBL + so + 16, gbl + 8);
        if (c < 18) {
            int p  = c >> 1;
            int hh = irow + p / 3 - 1;
            int ww = icol + p % 3 - 1;
            uint32_t ok = (((unsigned)hh < 48u) && ((unsigned)ww < 48u)) ? 16u : 0u;
            int hc = min(max(hh, 0), 47), wc = min(max(ww, 0), 47);
            const size_t gi = ((((size_t)b * 48 + hc) * 48 + wc) << 6)
                            + ((c & 1) << 5) + (sg << 3);
            cpa16z(base + OA  + so,      g_Fh + gi,     ok);
            cpa16z(base + OA  + so + 16, g_Fh + gi + 8, ok);
            cpa16z(base + OAL + so,      g_Fl + gi,     ok);
            cpa16z(base + OAL + so + 16, g_Fl + gi + 8, ok);
        } else {
            // tail: 18 rel, 2 cell, 12 zeros -> direct smem stores (hi/lo)
            float qcr = (float)(2 * irow + 1) / 48.0f - 1.0f;
            float qcc = (float)(2 * icol + 1) / 48.0f - 1.0f;
            bf16* dh = (bf16*)(smem + 512 + ps * STAGE + OA  + cr * (LDSR * 2));
            bf16* dl = (bf16*)(smem + 512 + ps * STAGE + OAL + cr * (LDSR * 2));
            #pragma unroll
            for (int t = 0; t < 16; t++) {
                int l = sg * 8 + t;
                float v;
                if (l < 18)      { float cv = cp[l]; v = (l & 1) ? (cv - qcc) : (cv - qcr) * 2304.0f; }
                else if (l < 20) { v = cell[(size_t)bq * 2 + (l - 18)] * 48.0f; }
                else             { v = 0.0f; }
                bf16 h, lo;
                split_bf16(v, h, lo);
                dh[l] = h; dl[l] = lo;
            }
        }
    };

    float acc[4][4][4];
    #pragma unroll
    for (int i = 0; i < 4; i++)
        #pragma unroll
        for (int j = 0; j < 4; j++)
            #pragma unroll
            for (int r = 0; r < 4; r++) acc[i][j][r] = 0.0f;

    load_chunk(0, 0);
    CP_COMMIT();

    for (int c = 0; c < 19; c++) {
        const int st = c & 1;
        if (c + 1 < 19) {
            load_chunk(c + 1, st ^ 1);
            CP_COMMIT();
            cp_wait<1>();
        } else {
            cp_wait<0>();
        }
        __syncthreads();
        uint32_t base = ST0 + (uint32_t)st * STAGE;
        MMA_CHUNK(base);
        __syncthreads();
    }

    EPILOGUE(g_H1h, g_H1l);
}

// ---------------- layers 1-3: bf16x3 GEMM on H planes ----------------
template<int AID, int CID, int WID>
__global__ void __launch_bounds__(256, 2) gemm_bf16x3(const float* __restrict__ bias)
{
    extern __shared__ char smem[];
    const bf16* Aph = (AID == 1) ? g_H1h : g_H2h;
    const bf16* Apl = (AID == 1) ? g_H1l : g_H2l;
    bf16*       Cph = (CID == 1) ? g_H1h : g_H2h;
    bf16*       Cpl = (CID == 1) ? g_H1l : g_H2l;
    const bf16* Wph = (WID == 1) ? g_W1h : ((WID == 2) ? g_W2h : g_W3h);
    const bf16* Wpl = (WID == 1) ? g_W1l : ((WID == 2) ? g_W2l : g_W3l);

    const int tid  = threadIdx.x;
    const int lane = tid & 31;
    const int wid  = tid >> 5;
    const int wm   = wid & 1;
    const int wn   = wid >> 1;
    const int bx   = blockIdx.x;
    const size_t row0 = (size_t)blockIdx.y * 128;

    float* bias_s = (float*)smem;
    if (tid < 128) bias_s[tid] = bias[bx * 128 + tid];

    const uint32_t sb  = smem_u32(smem);
    const uint32_t ST0 = sb + 512;

    FRAG_OFFSETS();

    const int cr = tid >> 1;
    const int sg = (tid & 1) << 1;

    auto load_chunk = [&](int c, int ps) {
        uint32_t base = ST0 + (uint32_t)ps * STAGE;
        uint32_t so   = (uint32_t)(cr * (LDSR * 2) + (sg << 4));
        const bf16* ga  = Aph + (row0 + cr) * HID + c * 32 + sg * 8;
        const bf16* gal = Apl + (row0 + cr) * HID + c * 32 + sg * 8;
        const bf16* gb  = Wph + (size_t)(bx * 128 + cr) * HID + c * 32 + sg * 8;
        const bf16* gbl = Wpl + (size_t)(bx * 128 + cr) * HID + c * 32 + sg * 8;
        cpa16(base + OA  + so,      ga);
        cpa16(base + OA  + so + 16, ga + 8);
        cpa16(base + OAL + so,      gal);
        cpa16(base + OAL + so + 16, gal + 8);
        cpa16(base + OB  + so,      gb);
        cpa16(base + OB  + so + 16, gb + 8);
        cpa16(base + OBL + so,      gbl);
        cpa16(base + OBL + so + 16, gbl + 8);
    };

    float acc[4][4][4];
    #pragma unroll
    for (int i = 0; i < 4; i++)
        #pragma unroll
        for (int j = 0; j < 4; j++)
            #pragma unroll
            for (int r = 0; r < 4; r++) acc[i][j][r] = 0.0f;

    load_chunk(0, 0);
    CP_COMMIT();

    for (int c = 0; c < 8; c++) {
        const int st = c & 1;
        if (c + 1 < 8) {
            load_chunk(c + 1, st ^ 1);
            CP_COMMIT();
            cp_wait<1>();
        } else {
            cp_wait<0>();
        }
        __syncthreads();
        uint32_t base = ST0 + (uint32_t)st * STAGE;
        MMA_CHUNK(base);
        __syncthreads();
    }

    EPILOGUE(Cph, Cpl);
}

// ---------------- fused blend + final 256 -> 27 GEMM + bias ----------------
__global__ void __launch_bounds__(256) final_fused(const float* __restrict__ w4,
                                                   const float* __restrict__ b4,
                                                   float* __restrict__ out)
{
    __shared__ float W4s[HID * OUTD];
    __shared__ float Hs[16][HID];

    int tid = threadIdx.x;
    for (int i = tid; i < HID * OUTD; i += 256) W4s[i] = w4[i];
    size_t row0 = (size_t)blockIdx.x * 16;
    const size_t CH = (size_t)BQ * HID;

    for (int i = tid; i < 16 * HID; i += 256) {
        int r = i >> 8, k = i & 255;
        int bq = (int)row0 + r;
        float a0 = g_area[bq];
        float a1 = g_area[BQ + bq];
        float a2 = g_area[2 * BQ + bq];
        float a3 = g_area[3 * BQ + bq];
        float inv = 1.0f / (a0 + a1 + a2 + a3);
        size_t off = (size_t)bq * HID + k;
        float v0 = __bfloat162float(g_H2h[off])          + __bfloat162float(g_H2l[off]);
        float v1 = __bfloat162float(g_H2h[CH + off])     + __bfloat162float(g_H2l[CH + off]);
        float v2 = __bfloat162float(g_H2h[2 * CH + off]) + __bfloat162float(g_H2l[2 * CH + off]);
        float v3 = __bfloat162float(g_H2h[3 * CH + off]) + __bfloat162float(g_H2l[3 * CH + off]);
        Hs[r][k] = (v0 * a3 + v1 * a2 + v2 * a1 + v3 * a0) * inv;
    }
    __syncthreads();

    for (int idx = tid; idx < 16 * OUTD; idx += 256) {
        int r = idx / OUTD, o = idx - r * OUTD;
        float s = 0.0f;
        #pragma unroll 8
        for (int k = 0; k < HID; k++) s += Hs[r][k] * W4s[k * OUTD + o];
        out[(row0 + r) * OUTD + o] = s + b4[o];
    }
}

// ---------------- launch ----------------
extern "C" void kernel_launch(void* const* d_in, const int* in_sizes, int n_in,
                              void* d_out, int out_size)
{
    const float* feat  = (const float*)d_in[0];
    const float* coord = (const float*)d_in[1];
    const float* cell  = (const float*)d_in[2];
    const float* w0 = (const float*)d_in[3];
    const float* b0 = (const float*)d_in[4];
    const float* w1 = (const float*)d_in[5];
    const float* b1 = (const float*)d_in[6];
    const float* w2 = (const float*)d_in[7];
    const float* b2 = (const float*)d_in[8];
    const float* w3 = (const float*)d_in[9];
    const float* b3 = (const float*)d_in[10];
    const float* w4 = (const float*)d_in[11];
    const float* b4 = (const float*)d_in[12];
    float* out = (float*)d_out;

    cudaFuncSetAttribute(gemm0_fused,         cudaFuncAttributeMaxDynamicSharedMemorySize, SMEM_BYTES);
    cudaFuncSetAttribute(gemm_bf16x3<1, 2, 1>, cudaFuncAttributeMaxDynamicSharedMemorySize, SMEM_BYTES);
    cudaFuncSetAttribute(gemm_bf16x3<2, 1, 2>, cudaFuncAttributeMaxDynamicSharedMemorySize, SMEM_BYTES);
    cudaFuncSetAttribute(gemm_bf16x3<1, 2, 3>, cudaFuncAttributeMaxDynamicSharedMemorySize, SMEM_BYTES);

    prep_weights<<<KIN, 256>>>(w0, w1, w2, w3);
    feat_prep   <<<(NBATCH * NH * NW * NCHAN + 255) / 256, 256>>>(feat);
    build_area  <<<NROWS / 256, 256>>>(coord);

    dim3 g(HID / 128, NROWS / 128);   // (2, 2048)
    gemm0_fused          <<<g, 256, SMEM_BYTES>>>(coord, cell, b0);  // feat-gather @ W0^T -> H1
    gemm_bf16x3<1, 2, 1> <<<g, 256, SMEM_BYTES>>>(b1);               // H1 @ W1^T -> H2
    gemm_bf16x3<2, 1, 2> <<<g, 256, SMEM_BYTES>>>(b2);               // H2 @ W2^T -> H1
    gemm_bf16x3<1, 2, 3> <<<g, 256, SMEM_BYTES>>>(b3);               // H1 @ W3^T -> H2

    final_fused<<<BQ / 16, 256>>>(w4, b4, out);
}

// round 10
// speedup vs baseline: 2.5525x; 1.1659x over previous
#include <cuda_runtime.h>
#include <cuda_bf16.h>
#include <math.h>
#include <cstdint>

// ---------------- problem constants ----------------
#define NBATCH 8
#define NCHAN  64
#define NH     48
#define NW     48
#define NQ     8192
#define BQ     (NBATCH * NQ)      // 65536 queries
#define NROWS  (4 * BQ)           // 262144 MLP rows (4 shifts)
#define KIN    608                // 596 padded to 608 (19 chunks of 32)
#define KREAL  596
#define HID    256
#define OUTD   27

typedef __nv_bfloat16 bf16;

// ---------------- device globals (allocation-free rule) ----------------
__device__ bf16  g_Fh [NBATCH * NH * NW * NCHAN];   // feat NHWC hi plane (2.25 MB)
__device__ bf16  g_Fl [NBATCH * NH * NW * NCHAN];
__device__ float g_Hc [(size_t)BQ * HID];           // blended hidden (67 MB)
__device__ bf16  g_W0h[HID * KIN];                  // w0^T, K-permuted (k' = p*64+c)
__device__ bf16  g_W0l[HID * KIN];
__device__ bf16  g_W1h[HID * HID];
__device__ bf16  g_W1l[HID * HID];
__device__ bf16  g_W2h[HID * HID];
__device__ bf16  g_W2l[HID * HID];
__device__ bf16  g_W3h[HID * HID];
__device__ bf16  g_W3l[HID * HID];

// ---------------- PTX helpers ----------------
__device__ __forceinline__ uint32_t smem_u32(const void* p) {
    uint32_t a;
    asm("{ .reg .u64 t; cvta.to.shared.u64 t, %1; cvt.u32.u64 %0, t; }" : "=r"(a) : "l"(p));
    return a;
}
__device__ __forceinline__ void cpa16(uint32_t s, const void* g) {
    asm volatile("cp.async.cg.shared.global [%0], [%1], 16;" :: "r"(s), "l"(g));
}
__device__ __forceinline__ void cpa16z(uint32_t s, const void* g, uint32_t n) {
    asm volatile("cp.async.cg.shared.global [%0], [%1], 16, %2;" :: "r"(s), "l"(g), "r"(n));
}
#define CP_COMMIT() asm volatile("cp.async.commit_group;" ::: "memory")
template<int N>
__device__ __forceinline__ void cp_wait() {
    asm volatile("cp.async.wait_group %0;" :: "n"(N) : "memory");
}
__device__ __forceinline__ void ldsm4(uint32_t (&r)[4], uint32_t addr) {
    asm volatile("ldmatrix.sync.aligned.m8n8.x4.shared.b16 {%0,%1,%2,%3}, [%4];"
        : "=r"(r[0]), "=r"(r[1]), "=r"(r[2]), "=r"(r[3]) : "r"(addr));
}
__device__ __forceinline__ void mma16816(float (&c)[4], const uint32_t (&a)[4],
                                         uint32_t b0, uint32_t b1) {
    asm volatile("mma.sync.aligned.m16n8k16.row.col.f32.bf16.bf16.f32 "
        "{%0,%1,%2,%3}, {%4,%5,%6,%7}, {%8,%9}, {%0,%1,%2,%3};"
        : "+f"(c[0]), "+f"(c[1]), "+f"(c[2]), "+f"(c[3])
        : "r"(a[0]), "r"(a[1]), "r"(a[2]), "r"(a[3]), "r"(b0), "r"(b1));
}
__device__ __forceinline__ void split_bf16(float v, bf16& h, bf16& l) {
    h = __float2bfloat16(v);
    l = __float2bfloat16(v - __bfloat162float(h));
}

// ---------------- smem layout (dynamic, one CTA/SM) ----------------
// A-buffer: 128 rows x 264 bf16 (stride 528 B -> conflict-free ldmatrix), hi+lo planes.
// Gather stages for layer 0 OVERLAY the A-buffer (dead before epilogue writes it).
#define ASTRIDE  528
#define ABUF_LO  67584                 // lo plane offset inside A-buf
#define G_STAGE  20480                 // layer-0 gather stage (Ah 10240 + Al 10240)
#define OFF_BST  135168                // B stream: 2 stages x (Bh 20480 + Bl 20480)
#define BSTAGE   40960
#define OFF_BIAS 217088                // 256 f32
#define OFF_AREA 218112                // 128 f32
#define SMEM_TOTAL 218624

// ---------------- weight prep: transpose + hi/lo split (+ K-permute for w0) ----
__global__ void prep_weights(const float* __restrict__ w0, const float* __restrict__ w1,
                             const float* __restrict__ w2, const float* __restrict__ w3)
{
    int idx = blockIdx.x * 256 + threadIdx.x;      // grid 608 -> 155648
    if (idx < HID * KIN) {
        int n = idx / KIN, kp = idx - n * KIN;
        int ko;
        if (kp < 576) { int p = kp >> 6, c = kp & 63; ko = c * 9 + p; }
        else          { ko = kp; }
        float v = (kp < KREAL) ? w0[ko * HID + n] : 0.0f;
        split_bf16(v, g_W0h[idx], g_W0l[idx]);
    }
    if (idx < HID * HID) {
        int n = idx >> 8, k = idx & 255;
        split_bf16(w1[k * HID + n], g_W1h[idx], g_W1l[idx]);
        split_bf16(w2[k * HID + n], g_W2h[idx], g_W2l[idx]);
        split_bf16(w3[k * HID + n], g_W3h[idx], g_W3l[idx]);
    }
}

// ---------------- feat -> NHWC bf16 hi/lo planes ----------------
__global__ void feat_prep(const float* __restrict__ feat)
{
    int idx = blockIdx.x * 256 + threadIdx.x;
    if (idx >= NBATCH * NH * NW * NCHAN) return;
    int t = idx;
    int c = t & 63; t >>= 6;
    int w = t % 48; t /= 48;
    int h = t % 48; int b = t / 48;
    float v = feat[(((size_t)b * 64 + c) * 48 + h) * 48 + w];
    split_bf16(v, g_Fh[idx], g_Fl[idx]);
}

// ---------------- coordinate helper ----------------
__device__ __forceinline__ void calc_rc(const float* cp, int s, int& row, int& col)
{
    const float SP  = (float)( 1.0 / 48.0 + 1e-6);
    const float SN  = (float)(-1.0 / 48.0 + 1e-6);
    const float CLO = (float)(-1.0 + 1e-6);
    const float CHI = (float)( 1.0 - 1e-6);
    float cx = cp[8] + ((s & 2) ? SP : SN);
    float cy = cp[9] + ((s & 1) ? SP : SN);
    cx = fminf(fmaxf(cx, CLO), CHI);
    cy = fminf(fmaxf(cy, CLO), CHI);
    row = (int)rintf((cx + 1.0f) * 24.0f - 0.5f);
    col = (int)rintf((cy + 1.0f) * 24.0f - 0.5f);
    row = min(max(row, 0), NH - 1);
    col = min(max(col, 0), NW - 1);
}

// ---------------- MMA step: 3-term bf16 split, warp tile 32x64 ----------------
#define MMA_STEP(AHB, ALB, AOFF, AKO, BHB, BLB, BKO)                                 \
    do {                                                                             \
        uint32_t ah[2][4], bh[4][4];                                                 \
        _Pragma("unroll")                                                            \
        for (int i = 0; i < 2; i++) ldsm4(ah[i], (AHB) + (AOFF)[i] + (AKO));         \
        _Pragma("unroll")                                                            \
        for (int j = 0; j < 4; j++) ldsm4(bh[j], (BHB) + boff[j] + (BKO));           \
        _Pragma("unroll")                                                            \
        for (int i = 0; i < 2; i++)                                                  \
            _Pragma("unroll")                                                        \
            for (int j = 0; j < 4; j++)                                              \
                _Pragma("unroll")                                                    \
                for (int h = 0; h < 2; h++)                                          \
                    mma16816(acc[i][j * 2 + h], ah[i], bh[j][2 * h], bh[j][2 * h + 1]); \
        uint32_t al[2][4];                                                           \
        _Pragma("unroll")                                                            \
        for (int i = 0; i < 2; i++) ldsm4(al[i], (ALB) + (AOFF)[i] + (AKO));         \
        _Pragma("unroll")                                                            \
        for (int i = 0; i < 2; i++)                                                  \
            _Pragma("unroll")                                                        \
            for (int j = 0; j < 4; j++)                                              \
                _Pragma("unroll")                                                    \
                for (int h = 0; h < 2; h++)                                          \
                    mma16816(acc[i][j * 2 + h], al[i], bh[j][2 * h], bh[j][2 * h + 1]); \
        uint32_t bl[4][4];                                                           \
        _Pragma("unroll")                                                            \
        for (int j = 0; j < 4; j++) ldsm4(bl[j], (BLB) + boff[j] + (BKO));           \
        _Pragma("unroll")                                                            \
        for (int i = 0; i < 2; i++)                                                  \
            _Pragma("unroll")                                                        \
            for (int j = 0; j < 4; j++)                                              \
                _Pragma("unroll")                                                    \
                for (int h = 0; h < 2; h++)                                          \
                    mma16816(acc[i][j * 2 + h], ah[i], bl[j][2 * h], bl[j][2 * h + 1]); \
    } while (0)

#define ZERO_ACC()                                                                   \
    _Pragma("unroll")                                                                \
    for (int i = 0; i < 2; i++)                                                      \
        _Pragma("unroll")                                                            \
        for (int j = 0; j < 8; j++)                                                  \
            _Pragma("unroll")                                                        \
            for (int r = 0; r < 4; r++) acc[i][j][r] = 0.0f;

// epilogue: relu(acc+bias), split hi/lo, write into smem A-buffer
#define EPI_TO_SMEM()                                                                \
    _Pragma("unroll")                                                                \
    for (int i = 0; i < 2; i++) {                                                    \
        const int r0 = wm * 32 + i * 16 + (lane >> 2);                               \
        _Pragma("unroll")                                                            \
        for (int jj = 0; jj < 8; jj++) {                                             \
            const int ncl = wn * 64 + jj * 8 + (lane & 3) * 2;                       \
            const float bz0 = biasS[ncl], bz1 = biasS[ncl + 1];                      \
            _Pragma("unroll")                                                        \
            for (int p = 0; p < 2; p++) {                                            \
                float v0 = fmaxf(acc[i][jj][2 * p + 0] + bz0, 0.0f);                 \
                float v1 = fmaxf(acc[i][jj][2 * p + 1] + bz1, 0.0f);                 \
                bf16 h0, l0, h1, l1;                                                 \
                split_bf16(v0, h0, l0);                                              \
                split_bf16(v1, h1, l1);                                              \
                const int row = r0 + p * 8;                                          \
                *(__nv_bfloat162*)(smem + row * ASTRIDE + ncl * 2)                   \
                    = __nv_bfloat162(h0, h1);                                        \
                *(__nv_bfloat162*)(smem + ABUF_LO + row * ASTRIDE + ncl * 2)         \
                    = __nv_bfloat162(l0, l1);                                        \
            }                                                                        \
        }                                                                            \
    }

// ---------------- fused MLP: layers 0-3 + blend, one CTA = 128 rows ----------------
// Row order: grow = bq*4 + s  (all 4 shifts of a query adjacent -> CTA-local blend)
__global__ void __launch_bounds__(512, 1)
mlp_fused(const float* __restrict__ coord, const float* __restrict__ cell,
          const float* __restrict__ b0, const float* __restrict__ b1,
          const float* __restrict__ b2, const float* __restrict__ b3)
{
    extern __shared__ char smem[];
    const int tid  = threadIdx.x;
    const int lane = tid & 31;
    const int wid  = tid >> 5;
    const int wm   = wid & 3;        // M group (32 rows)
    const int wn   = wid >> 2;       // N group (64 cols)
    const int row0 = blockIdx.x * 128;
    const int bq0  = blockIdx.x * 32;

    float* biasS = (float*)(smem + OFF_BIAS);
    float* areaS = (float*)(smem + OFF_AREA);
    const uint32_t sb = smem_u32(smem);

    // ---- gather identity for this thread (4 threads per row) ----
    const int cr = tid >> 2;         // local row 0..127
    const int sg = tid & 3;          // 16B segment 0..3
    const int grow = row0 + cr;
    const int gbq  = grow >> 2;
    const int gs   = grow & 3;
    const int gb   = gbq >> 13;
    const float* cpr = coord + (size_t)gbq * 18;
    int irow, icol;
    calc_rc(cpr, gs, irow, icol);
    const float qcr_r = (float)(2 * irow + 1) / 48.0f - 1.0f;
    const float qcc_r = (float)(2 * icol + 1) / 48.0f - 1.0f;

    // ---- per-row area (1 thread per row) ----
    if (tid < 128) {
        int gr = row0 + tid;
        int bq = gr >> 2, s = gr & 3;
        const float* cp = coord + (size_t)bq * 18;
        int r, c;
        calc_rc(cp, s, r, c);
        float qr = (float)(2 * r + 1) / 48.0f - 1.0f;
        float qc = (float)(2 * c + 1) / 48.0f - 1.0f;
        float ax = (cp[0] - qr) * 2304.0f;
        float ay = (cp[1] - qc);
        areaS[tid] = fabsf(ax * ay) + 1e-9f;
    }
    if (tid < 256) biasS[tid] = b0[tid];

    // ---- fragment offsets ----
    uint32_t aoff0[2], aoffA[2], boff[4];
    #pragma unroll
    for (int i = 0; i < 2; i++) {
        int rb = wm * 32 + i * 16 + (lane & 15);
        aoff0[i] = (uint32_t)(rb * 80)      + ((lane >> 4) << 4);
        aoffA[i] = (uint32_t)(rb * ASTRIDE) + ((lane >> 4) << 4);
    }
    #pragma unroll
    for (int j = 0; j < 4; j++) {
        int rb = wn * 64 + j * 16 + (lane & 7) + ((lane >> 4) << 3);
        boff[j] = (uint32_t)(rb * 80) + (((lane >> 3) & 1) << 4);
    }

    // ---- loaders ----
    const int br  = tid >> 1;        // B row 0..255
    const int b2s = (tid & 1) << 1;  // B segment pair {0,1} or {2,3}

    auto load0 = [&](int c, int ps) {
        // B = W0 chunk
        uint32_t bb = sb + OFF_BST + (uint32_t)ps * BSTAGE;
        uint32_t bo = (uint32_t)(br * 80) + ((uint32_t)b2s << 4);
        const bf16* gbh = g_W0h + (size_t)br * KIN + c * 32 + b2s * 8;
        const bf16* gbl = g_W0l + (size_t)br * KIN + c * 32 + b2s * 8;
        cpa16(bb + bo,              gbh);
        cpa16(bb + bo + 16,         gbh + 8);
        cpa16(bb + 20480 + bo,      gbl);
        cpa16(bb + 20480 + bo + 16, gbl + 8);
        // A gather (overlays A-buf region)
        uint32_t ab = sb + (uint32_t)ps * G_STAGE;
        uint32_t ao = (uint32_t)(cr * 80) + ((uint32_t)sg << 4);
        if (c < 18) {
            int p  = c >> 1;
            int hh = irow + p / 3 - 1;
            int ww = icol + p % 3 - 1;
            uint32_t ok = (((unsigned)hh < 48u) && ((unsigned)ww < 48u)) ? 16u : 0u;
            int hc = min(max(hh, 0), 47), wc = min(max(ww, 0), 47);
            size_t gi = ((((size_t)gb * 48 + hc) * 48 + wc) << 6)
                      + ((c & 1) << 5) + (sg << 3);
            cpa16z(ab + ao,         g_Fh + gi, ok);
            cpa16z(ab + 10240 + ao, g_Fl + gi, ok);
        } else {
            bf16* dh = (bf16*)(smem + ps * G_STAGE + cr * 80);
            bf16* dl = dh + 5120;
            #pragma unroll
            for (int t = 0; t < 8; t++) {
                int l = sg * 8 + t;
                float v;
                if (l < 18)      { float cv = cpr[l]; v = (l & 1) ? (cv - qcc_r) : (cv - qcr_r) * 2304.0f; }
                else if (l < 20) { v = cell[(size_t)gbq * 2 + (l - 18)] * 48.0f; }
                else             { v = 0.0f; }
                bf16 h, lo;
                split_bf16(v, h, lo);
                dh[l] = h; dl[l] = lo;
            }
        }
    };

    auto loadB = [&](const bf16* Wh, const bf16* Wl, int c, int ps) {
        uint32_t bb = sb + OFF_BST + (uint32_t)ps * BSTAGE;
        uint32_t bo = (uint32_t)(br * 80) + ((uint32_t)b2s << 4);
        const bf16* gbh = Wh + (size_t)br * HID + c * 32 + b2s * 8;
        const bf16* gbl = Wl + (size_t)br * HID + c * 32 + b2s * 8;
        cpa16(bb + bo,              gbh);
        cpa16(bb + bo + 16,         gbh + 8);
        cpa16(bb + 20480 + bo,      gbl);
        cpa16(bb + 20480 + bo + 16, gbl + 8);
    };

    float acc[2][8][4];
    ZERO_ACC();

    // ================= layer 0: fused gather GEMM (K=608, 19 chunks) =================
    load0(0, 0);
    CP_COMMIT();
    for (int c = 0; c < 19; c++) {
        const int st = c & 1;
        if (c + 1 < 19) { load0(c + 1, st ^ 1); CP_COMMIT(); cp_wait<1>(); }
        else            { cp_wait<0>(); }
        __syncthreads();
        uint32_t ahb = sb + (uint32_t)st * G_STAGE;
        uint32_t alb = ahb + 10240;
        uint32_t bhb = sb + OFF_BST + (uint32_t)st * BSTAGE;
        uint32_t blb = bhb + 20480;
        MMA_STEP(ahb, alb, aoff0, 0u,  bhb, blb, 0u);
        MMA_STEP(ahb, alb, aoff0, 32u, bhb, blb, 32u);
        __syncthreads();
    }
    EPI_TO_SMEM();           // gather stages dead; write H1 planes into A-buf
    __syncthreads();

    // ================= layers 1-3: A resident in smem =================
    const bf16* WH[3] = { g_W1h, g_W2h, g_W3h };
    const bf16* WL[3] = { g_W1l, g_W2l, g_W3l };
    const float* BB[3] = { b1, b2, b3 };

    for (int L = 0; L < 3; L++) {
        if (tid < 256) biasS[tid] = BB[L][tid];
        ZERO_ACC();
        loadB(WH[L], WL[L], 0, 0);
        CP_COMMIT();
        for (int c = 0; c < 8; c++) {
            const int st = c & 1;
            if (c + 1 < 8) { loadB(WH[L], WL[L], c + 1, st ^ 1); CP_COMMIT(); cp_wait<1>(); }
            else           { cp_wait<0>(); }
            __syncthreads();
            uint32_t ahb = sb;
            uint32_t alb = sb + ABUF_LO;
            uint32_t bhb = sb + OFF_BST + (uint32_t)st * BSTAGE;
            uint32_t blb = bhb + 20480;
            const uint32_t ako = (uint32_t)(c << 6);
            MMA_STEP(ahb, alb, aoffA, ako,       bhb, blb, 0u);
            MMA_STEP(ahb, alb, aoffA, ako + 32u, bhb, blb, 32u);
            __syncthreads();
        }
        EPI_TO_SMEM();       // trailing sync of c=7 guarantees all reads done
        __syncthreads();
    }

    // ================= blend across shifts, write fp32 Hc =================
    for (int idx = tid; idx < 32 * HID; idx += 512) {
        const int q = idx >> 8, k = idx & 255;
        float a0 = areaS[q * 4 + 0];
        float a1 = areaS[q * 4 + 1];
        float a2 = areaS[q * 4 + 2];
        float a3 = areaS[q * 4 + 3];
        float inv = 1.0f / (a0 + a1 + a2 + a3);
        float hc = 0.0f;
        #pragma unroll
        for (int s = 0; s < 4; s++) {
            const int row = q * 4 + s;
            float h = __bfloat162float(*(const bf16*)(smem + row * ASTRIDE + k * 2))
                    + __bfloat162float(*(const bf16*)(smem + ABUF_LO + row * ASTRIDE + k * 2));
            float w = (s == 0) ? a3 : (s == 1) ? a2 : (s == 2) ? a1 : a0;
            hc += h * w;
        }
        g_Hc[(size_t)(bq0 + q) * HID + k] = hc * inv;
    }
}

// ---------------- final 256 -> 27 GEMM + bias ----------------
__global__ void __launch_bounds__(256) final_gemm(const float* __restrict__ w4,
                                                  const float* __restrict__ b4,
                                                  float* __restrict__ out)
{
    __shared__ float W4s[HID * OUTD];
    __shared__ float Hs[16][HID];

    int tid = threadIdx.x;
    for (int i = tid; i < HID * OUTD; i += 256) W4s[i] = w4[i];
    size_t row0 = (size_t)blockIdx.x * 16;
    for (int i = tid; i < 16 * HID; i += 256)
        Hs[i >> 8][i & 255] = g_Hc[(row0 + (size_t)(i >> 8)) * HID + (i & 255)];
    __syncthreads();

    for (int idx = tid; idx < 16 * OUTD; idx += 256) {
        int r = idx / OUTD, o = idx - r * OUTD;
        float s = 0.0f;
        #pragma unroll 8
        for (int k = 0; k < HID; k++) s += Hs[r][k] * W4s[k * OUTD + o];
        out[(row0 + r) * OUTD + o] = s + b4[o];
    }
}

// ---------------- launch ----------------
extern "C" void kernel_launch(void* const* d_in, const int* in_sizes, int n_in,
                              void* d_out, int out_size)
{
    const float* feat  = (const float*)d_in[0];
    const float* coord = (const float*)d_in[1];
    const float* cell  = (const float*)d_in[2];
    const float* w0 = (const float*)d_in[3];
    const float* b0 = (const float*)d_in[4];
    const float* w1 = (const float*)d_in[5];
    const float* b1 = (const float*)d_in[6];
    const float* w2 = (const float*)d_in[7];
    const float* b2 = (const float*)d_in[8];
    const float* w3 = (const float*)d_in[9];
    const float* b3 = (const float*)d_in[10];
    const float* w4 = (const float*)d_in[11];
    const float* b4 = (const float*)d_in[12];
    float* out = (float*)d_out;

    cudaFuncSetAttribute(mlp_fused, cudaFuncAttributeMaxDynamicSharedMemorySize, SMEM_TOTAL);

    prep_weights<<<KIN, 256>>>(w0, w1, w2, w3);
    feat_prep   <<<(NBATCH * NH * NW * NCHAN + 255) / 256, 256>>>(feat);

    mlp_fused<<<NROWS / 128, 512, SMEM_TOTAL>>>(coord, cell, b0, b1, b2, b3);

    final_gemm<<<BQ / 16, 256>>>(w4, b4, out);
}

// round 11
// speedup vs baseline: 2.5897x; 1.0146x over previous
#include <cuda_runtime.h>
#include <cuda_bf16.h>
#include <math.h>
#include <cstdint>

// ---------------- problem constants ----------------
#define NBATCH 8
#define NCHAN  64
#define NH     48
#define NW     48
#define NQ     8192
#define BQ     (NBATCH * NQ)      // 65536 queries
#define NROWS  (4 * BQ)           // 262144 MLP rows (4 shifts)
#define KIN    608                // 596 padded to 608 (19 chunks of 32)
#define KREAL  596
#define HID    256
#define OUTD   27

typedef __nv_bfloat16 bf16;

// ---------------- device globals (allocation-free rule) ----------------
__device__ bf16  g_Fh [NBATCH * NH * NW * NCHAN];   // feat NHWC hi plane (2.25 MB)
__device__ bf16  g_Fl [NBATCH * NH * NW * NCHAN];
__device__ bf16  g_W0h[HID * KIN];                  // w0^T, K-permuted (k' = p*64+c)
__device__ bf16  g_W0l[HID * KIN];
__device__ bf16  g_W1h[HID * HID];
__device__ bf16  g_W1l[HID * HID];
__device__ bf16  g_W2h[HID * HID];
__device__ bf16  g_W2l[HID * HID];
__device__ bf16  g_W3h[HID * HID];
__device__ bf16  g_W3l[HID * HID];
__device__ float g_W4t[OUTD * 260];                 // w4^T, row-padded to 260 fp32

// ---------------- PTX helpers ----------------
__device__ __forceinline__ uint32_t smem_u32(const void* p) {
    uint32_t a;
    asm("{ .reg .u64 t; cvta.to.shared.u64 t, %1; cvt.u32.u64 %0, t; }" : "=r"(a) : "l"(p));
    return a;
}
__device__ __forceinline__ void cpa16(uint32_t s, const void* g) {
    asm volatile("cp.async.cg.shared.global [%0], [%1], 16;" :: "r"(s), "l"(g));
}
__device__ __forceinline__ void cpa16z(uint32_t s, const void* g, uint32_t n) {
    asm volatile("cp.async.cg.shared.global [%0], [%1], 16, %2;" :: "r"(s), "l"(g), "r"(n));
}
#define CP_COMMIT() asm volatile("cp.async.commit_group;" ::: "memory")
template<int N>
__device__ __forceinline__ void cp_wait() {
    asm volatile("cp.async.wait_group %0;" :: "n"(N) : "memory");
}
__device__ __forceinline__ void ldsm4(uint32_t (&r)[4], uint32_t addr) {
    asm volatile("ldmatrix.sync.aligned.m8n8.x4.shared.b16 {%0,%1,%2,%3}, [%4];"
        : "=r"(r[0]), "=r"(r[1]), "=r"(r[2]), "=r"(r[3]) : "r"(addr));
}
__device__ __forceinline__ void mma16816(float (&c)[4], const uint32_t (&a)[4],
                                         uint32_t b0, uint32_t b1) {
    asm volatile("mma.sync.aligned.m16n8k16.row.col.f32.bf16.bf16.f32 "
        "{%0,%1,%2,%3}, {%4,%5,%6,%7}, {%8,%9}, {%0,%1,%2,%3};"
        : "+f"(c[0]), "+f"(c[1]), "+f"(c[2]), "+f"(c[3])
        : "r"(a[0]), "r"(a[1]), "r"(a[2]), "r"(a[3]), "r"(b0), "r"(b1));
}
__device__ __forceinline__ void split_bf16(float v, bf16& h, bf16& l) {
    h = __float2bfloat16(v);
    l = __float2bfloat16(v - __bfloat162float(h));
}

// ---------------- smem layout (dynamic, one CTA/SM) ----------------
#define ASTRIDE  528
#define ABUF_LO  67584                 // lo plane offset inside A-buf
#define G_STAGE  20480                 // layer-0 gather stage (Ah 10240 + Al 10240)
#define OFF_BST  135168                // B stream: 2 stages x (Bh 20480 + Bl 20480)
#define BSTAGE   40960
// after the last layer, the B-stream region is dead; overlay w4^T + Hc there
#define OFF_W4   135168                // 27 x 260 fp32 = 28080 B
#define OFF_HC   163264                // 32 x 260 fp32 = 33280 B (ends 196544)
#define OFF_BIAS 217088                // 256 f32
#define OFF_AREA 218112                // 128 f32
#define SMEM_TOTAL 218624

// ---------------- weight prep: transpose + hi/lo split (+ K-permute for w0) ----
__global__ void prep_weights(const float* __restrict__ w0, const float* __restrict__ w1,
                             const float* __restrict__ w2, const float* __restrict__ w3,
                             const float* __restrict__ w4)
{
    int idx = blockIdx.x * 256 + threadIdx.x;      // grid 608 -> 155648
    if (idx < HID * KIN) {
        int n = idx / KIN, kp = idx - n * KIN;
        int ko;
        if (kp < 576) { int p = kp >> 6, c = kp & 63; ko = c * 9 + p; }
        else          { ko = kp; }
        float v = (kp < KREAL) ? w0[ko * HID + n] : 0.0f;
        split_bf16(v, g_W0h[idx], g_W0l[idx]);
    }
    if (idx < HID * HID) {
        int n = idx >> 8, k = idx & 255;
        split_bf16(w1[k * HID + n], g_W1h[idx], g_W1l[idx]);
        split_bf16(w2[k * HID + n], g_W2h[idx], g_W2l[idx]);
        split_bf16(w3[k * HID + n], g_W3h[idx], g_W3l[idx]);
    }
    if (idx < OUTD * HID) {
        int o = idx >> 8, k = idx & 255;
        g_W4t[o * 260 + k] = w4[k * OUTD + o];
    }
}

// ---------------- feat -> NHWC bf16 hi/lo planes ----------------
__global__ void feat_prep(const float* __restrict__ feat)
{
    int idx = blockIdx.x * 256 + threadIdx.x;
    if (idx >= NBATCH * NH * NW * NCHAN) return;
    int t = idx;
    int c = t & 63; t >>= 6;
    int w = t % 48; t /= 48;
    int h = t % 48; int b = t / 48;
    float v = feat[(((size_t)b * 64 + c) * 48 + h) * 48 + w];
    split_bf16(v, g_Fh[idx], g_Fl[idx]);
}

// ---------------- coordinate helper ----------------
__device__ __forceinline__ void calc_rc(const float* cp, int s, int& row, int& col)
{
    const float SP  = (float)( 1.0 / 48.0 + 1e-6);
    const float SN  = (float)(-1.0 / 48.0 + 1e-6);
    const float CLO = (float)(-1.0 + 1e-6);
    const float CHI = (float)( 1.0 - 1e-6);
    float cx = cp[8] + ((s & 2) ? SP : SN);
    float cy = cp[9] + ((s & 1) ? SP : SN);
    cx = fminf(fmaxf(cx, CLO), CHI);
    cy = fminf(fmaxf(cy, CLO), CHI);
    row = (int)rintf((cx + 1.0f) * 24.0f - 0.5f);
    col = (int)rintf((cy + 1.0f) * 24.0f - 0.5f);
    row = min(max(row, 0), NH - 1);
    col = min(max(col, 0), NW - 1);
}

// ---------------- MMA step: 3-term bf16 split, warp tile 32x64 ----------------
#define MMA_STEP(AHB, ALB, AOFF, AKO, BHB, BLB, BKO)                                 \
    do {                                                                             \
        uint32_t ah[2][4], bh[4][4];                                                 \
        _Pragma("unroll")                                                            \
        for (int i = 0; i < 2; i++) ldsm4(ah[i], (AHB) + (AOFF)[i] + (AKO));         \
        _Pragma("unroll")                                                            \
        for (int j = 0; j < 4; j++) ldsm4(bh[j], (BHB) + boff[j] + (BKO));           \
        _Pragma("unroll")                                                            \
        for (int i = 0; i < 2; i++)                                                  \
            _Pragma("unroll")                                                        \
            for (int j = 0; j < 4; j++)                                              \
                _Pragma("unroll")                                                    \
                for (int h = 0; h < 2; h++)                                          \
                    mma16816(acc[i][j * 2 + h], ah[i], bh[j][2 * h], bh[j][2 * h + 1]); \
        uint32_t al[2][4];                                                           \
        _Pragma("unroll")                                                            \
        for (int i = 0; i < 2; i++) ldsm4(al[i], (ALB) + (AOFF)[i] + (AKO));         \
        _Pragma("unroll")                                                            \
        for (int i = 0; i < 2; i++)                                                  \
            _Pragma("unroll")                                                        \
            for (int j = 0; j < 4; j++)                                              \
                _Pragma("unroll")                                                    \
                for (int h = 0; h < 2; h++)                                          \
                    mma16816(acc[i][j * 2 + h], al[i], bh[j][2 * h], bh[j][2 * h + 1]); \
        uint32_t bl[4][4];                                                           \
        _Pragma("unroll")                                                            \
        for (int j = 0; j < 4; j++) ldsm4(bl[j], (BLB) + boff[j] + (BKO));           \
        _Pragma("unroll")                                                            \
        for (int i = 0; i < 2; i++)                                                  \
            _Pragma("unroll")                                                        \
            for (int j = 0; j < 4; j++)                                              \
                _Pragma("unroll")                                                    \
                for (int h = 0; h < 2; h++)                                          \
                    mma16816(acc[i][j * 2 + h], ah[i], bl[j][2 * h], bl[j][2 * h + 1]); \
    } while (0)

#define ZERO_ACC()                                                                   \
    _Pragma("unroll")                                                                \
    for (int i = 0; i < 2; i++)                                                      \
        _Pragma("unroll")                                                            \
        for (int j = 0; j < 8; j++)                                                  \
            _Pragma("unroll")                                                        \
            for (int r = 0; r < 4; r++) acc[i][j][r] = 0.0f;

// epilogue: relu(acc+bias), split hi/lo, write into smem A-buffer
#define EPI_TO_SMEM()                                                                \
    _Pragma("unroll")                                                                \
    for (int i = 0; i < 2; i++) {                                                    \
        const int r0 = wm * 32 + i * 16 + (lane >> 2);                               \
        _Pragma("unroll")                                                            \
        for (int jj = 0; jj < 8; jj++) {                                             \
            const int ncl = wn * 64 + jj * 8 + (lane & 3) * 2;                       \
            const float bz0 = biasS[ncl], bz1 = biasS[ncl + 1];                      \
            _Pragma("unroll")                                                        \
            for (int p = 0; p < 2; p++) {                                            \
                float v0 = fmaxf(acc[i][jj][2 * p + 0] + bz0, 0.0f);                 \
                float v1 = fmaxf(acc[i][jj][2 * p + 1] + bz1, 0.0f);                 \
                bf16 h0, l0, h1, l1;                                                 \
                split_bf16(v0, h0, l0);                                              \
                split_bf16(v1, h1, l1);                                              \
                const int row = r0 + p * 8;                                          \
                *(__nv_bfloat162*)(smem + row * ASTRIDE + ncl * 2)                   \
                    = __nv_bfloat162(h0, h1);                                        \
                *(__nv_bfloat162*)(smem + ABUF_LO + row * ASTRIDE + ncl * 2)         \
                    = __nv_bfloat162(l0, l1);                                        \
            }                                                                        \
        }                                                                            \
    }

// ---------------- fused MLP: layers 0-3 + blend + final GEMM, one CTA = 128 rows --
// Row order: grow = bq*4 + s  (all 4 shifts of a query adjacent -> CTA-local blend)
__global__ void __launch_bounds__(512, 1)
mlp_fused(const float* __restrict__ coord, const float* __restrict__ cell,
          const float* __restrict__ b0, const float* __restrict__ b1,
          const float* __restrict__ b2, const float* __restrict__ b3,
          const float* __restrict__ b4, float* __restrict__ out)
{
    extern __shared__ char smem[];
    const int tid  = threadIdx.x;
    const int lane = tid & 31;
    const int wid  = tid >> 5;
    const int wm   = wid & 3;        // M group (32 rows)
    const int wn   = wid >> 2;       // N group (64 cols)
    const int row0 = blockIdx.x * 128;
    const int bq0  = blockIdx.x * 32;

    float* biasS = (float*)(smem + OFF_BIAS);
    float* areaS = (float*)(smem + OFF_AREA);
    const uint32_t sb = smem_u32(smem);

    // ---- gather identity for this thread (4 threads per row) ----
    const int cr = tid >> 2;         // local row 0..127
    const int sg = tid & 3;          // 16B segment 0..3
    const int grow = row0 + cr;
    const int gbq  = grow >> 2;
    const int gs   = grow & 3;
    const int gb   = gbq >> 13;
    const float* cpr = coord + (size_t)gbq * 18;
    int irow, icol;
    calc_rc(cpr, gs, irow, icol);
    const float qcr_r = (float)(2 * irow + 1) / 48.0f - 1.0f;
    const float qcc_r = (float)(2 * icol + 1) / 48.0f - 1.0f;

    // ---- per-row area (1 thread per row) ----
    if (tid < 128) {
        int gr = row0 + tid;
        int bq = gr >> 2, s = gr & 3;
        const float* cp = coord + (size_t)bq * 18;
        int r, c;
        calc_rc(cp, s, r, c);
        float qr = (float)(2 * r + 1) / 48.0f - 1.0f;
        float qc = (float)(2 * c + 1) / 48.0f - 1.0f;
        float ax = (cp[0] - qr) * 2304.0f;
        float ay = (cp[1] - qc);
        areaS[tid] = fabsf(ax * ay) + 1e-9f;
    }
    if (tid < 256) biasS[tid] = b0[tid];

    // ---- fragment offsets ----
    uint32_t aoff0[2], aoffA[2], boff[4];
    #pragma unroll
    for (int i = 0; i < 2; i++) {
        int rb = wm * 32 + i * 16 + (lane & 15);
        aoff0[i] = (uint32_t)(rb * 80)      + ((lane >> 4) << 4);
        aoffA[i] = (uint32_t)(rb * ASTRIDE) + ((lane >> 4) << 4);
    }
    #pragma unroll
    for (int j = 0; j < 4; j++) {
        int rb = wn * 64 + j * 16 + (lane & 7) + ((lane >> 4) << 3);
        boff[j] = (uint32_t)(rb * 80) + (((lane >> 3) & 1) << 4);
    }

    // ---- loaders ----
    const int br  = tid >> 1;        // B row 0..255
    const int b2s = (tid & 1) << 1;  // B segment pair {0,1} or {2,3}

    auto load0 = [&](int c, int ps) {
        uint32_t bb = sb + OFF_BST + (uint32_t)ps * BSTAGE;
        uint32_t bo = (uint32_t)(br * 80) + ((uint32_t)b2s << 4);
        const bf16* gbh = g_W0h + (size_t)br * KIN + c * 32 + b2s * 8;
        const bf16* gbl = g_W0l + (size_t)br * KIN + c * 32 + b2s * 8;
        cpa16(bb + bo,              gbh);
        cpa16(bb + bo + 16,         gbh + 8);
        cpa16(bb + 20480 + bo,      gbl);
        cpa16(bb + 20480 + bo + 16, gbl + 8);
        uint32_t ab = sb + (uint32_t)ps * G_STAGE;
        uint32_t ao = (uint32_t)(cr * 80) + ((uint32_t)sg << 4);
        if (c < 18) {
            int p  = c >> 1;
            int hh = irow + p / 3 - 1;
            int ww = icol + p % 3 - 1;
            uint32_t ok = (((unsigned)hh < 48u) && ((unsigned)ww < 48u)) ? 16u : 0u;
            int hc = min(max(hh, 0), 47), wc = min(max(ww, 0), 47);
            size_t gi = ((((size_t)gb * 48 + hc) * 48 + wc) << 6)
                      + ((c & 1) << 5) + (sg << 3);
            cpa16z(ab + ao,         g_Fh + gi, ok);
            cpa16z(ab + 10240 + ao, g_Fl + gi, ok);
        } else {
            bf16* dh = (bf16*)(smem + ps * G_STAGE + cr * 80);
            bf16* dl = dh + 5120;
            #pragma unroll
            for (int t = 0; t < 8; t++) {
                int l = sg * 8 + t;
                float v;
                if (l < 18)      { float cv = cpr[l]; v = (l & 1) ? (cv - qcc_r) : (cv - qcr_r) * 2304.0f; }
                else if (l < 20) { v = cell[(size_t)gbq * 2 + (l - 18)] * 48.0f; }
                else             { v = 0.0f; }
                bf16 h, lo;
                split_bf16(v, h, lo);
                dh[l] = h; dl[l] = lo;
            }
        }
    };

    auto loadB = [&](const bf16* Wh, const bf16* Wl, int c, int ps) {
        uint32_t bb = sb + OFF_BST + (uint32_t)ps * BSTAGE;
        uint32_t bo = (uint32_t)(br * 80) + ((uint32_t)b2s << 4);
        const bf16* gbh = Wh + (size_t)br * HID + c * 32 + b2s * 8;
        const bf16* gbl = Wl + (size_t)br * HID + c * 32 + b2s * 8;
        cpa16(bb + bo,              gbh);
        cpa16(bb + bo + 16,         gbh + 8);
        cpa16(bb + 20480 + bo,      gbl);
        cpa16(bb + 20480 + bo + 16, gbl + 8);
    };

    float acc[2][8][4];
    ZERO_ACC();

    // ================= layer 0: fused gather GEMM (K=608, 19 chunks) =================
    load0(0, 0);
    CP_COMMIT();
    for (int c = 0; c < 19; c++) {
        const int st = c & 1;
        if (c + 1 < 19) { load0(c + 1, st ^ 1); CP_COMMIT(); cp_wait<1>(); }
        else            { cp_wait<0>(); }
        __syncthreads();
        uint32_t ahb = sb + (uint32_t)st * G_STAGE;
        uint32_t alb = ahb + 10240;
        uint32_t bhb = sb + OFF_BST + (uint32_t)st * BSTAGE;
        uint32_t blb = bhb + 20480;
        MMA_STEP(ahb, alb, aoff0, 0u,  bhb, blb, 0u);
        MMA_STEP(ahb, alb, aoff0, 32u, bhb, blb, 32u);
        __syncthreads();
    }
    EPI_TO_SMEM();
    __syncthreads();

    // ================= layers 1-3: A resident in smem =================
    const bf16* WH[3] = { g_W1h, g_W2h, g_W3h };
    const bf16* WL[3] = { g_W1l, g_W2l, g_W3l };
    const float* BB[3] = { b1, b2, b3 };

    for (int L = 0; L < 3; L++) {
        if (tid < 256) biasS[tid] = BB[L][tid];
        ZERO_ACC();
        loadB(WH[L], WL[L], 0, 0);
        CP_COMMIT();
        for (int c = 0; c < 8; c++) {
            const int st = c & 1;
            if (c + 1 < 8) { loadB(WH[L], WL[L], c + 1, st ^ 1); CP_COMMIT(); cp_wait<1>(); }
            else           { cp_wait<0>(); }
            __syncthreads();
            uint32_t ahb = sb;
            uint32_t alb = sb + ABUF_LO;
            uint32_t bhb = sb + OFF_BST + (uint32_t)st * BSTAGE;
            uint32_t blb = bhb + 20480;
            const uint32_t ako = (uint32_t)(c << 6);
            MMA_STEP(ahb, alb, aoffA, ako,       bhb, blb, 0u);
            MMA_STEP(ahb, alb, aoffA, ako + 32u, bhb, blb, 32u);
            __syncthreads();
        }
        EPI_TO_SMEM();
        __syncthreads();
    }

    // ================= stage w4^T into the dead B-stream region =================
    float* w4S = (float*)(smem + OFF_W4);
    float* hcS = (float*)(smem + OFF_HC);
    for (int i = tid; i < OUTD * HID; i += 512) {
        int o = i >> 8, k = i & 255;
        w4S[o * 260 + k] = g_W4t[o * 260 + k];
    }

    // ================= blend across shifts -> smem Hc (fp32) =================
    for (int idx = tid; idx < 32 * HID; idx += 512) {
        const int q = idx >> 8, k = idx & 255;
        float a0 = areaS[q * 4 + 0];
        float a1 = areaS[q * 4 + 1];
        float a2 = areaS[q * 4 + 2];
        float a3 = areaS[q * 4 + 3];
        float inv = 1.0f / (a0 + a1 + a2 + a3);
        float hc = 0.0f;
        #pragma unroll
        for (int s = 0; s < 4; s++) {
            const int row = q * 4 + s;
            float h = __bfloat162float(*(const bf16*)(smem + row * ASTRIDE + k * 2))
                    + __bfloat162float(*(const bf16*)(smem + ABUF_LO + row * ASTRIDE + k * 2));
            float w = (s == 0) ? a3 : (s == 1) ? a2 : (s == 2) ? a1 : a0;
            hc += h * w;
        }
        hcS[q * 260 + k] = hc * inv;
    }
    __syncthreads();

    // ================= final 256 -> 27 GEMM: warp q, lane o =================
    #pragma unroll
    for (int rep = 0; rep < 2; rep++) {
        const int q = wid * 2 + rep;
        if (lane < OUTD) {
            const float* hq = hcS + q * 260;
            const float* wo = w4S + lane * 260;
            float s = 0.0f;
            #pragma unroll 4
            for (int k = 0; k < HID; k += 4) {
                float4 h4 = *(const float4*)(hq + k);   // warp-broadcast
                float4 w4v = *(const float4*)(wo + k);
                s += h4.x * w4v.x + h4.y * w4v.y + h4.z * w4v.z + h4.w * w4v.w;
            }
            out[(size_t)(bq0 + q) * OUTD + lane] = s + __ldg(&b4[lane]);
        }
    }
}

// ---------------- launch ----------------
extern "C" void kernel_launch(void* const* d_in, const int* in_sizes, int n_in,
                              void* d_out, int out_size)
{
    const float* feat  = (const float*)d_in[0];
    const float* coord = (const float*)d_in[1];
    const float* cell  = (const float*)d_in[2];
    const float* w0 = (const float*)d_in[3];
    const float* b0 = (const float*)d_in[4];
    const float* w1 = (const float*)d_in[5];
    const float* b1 = (const float*)d_in[6];
    const float* w2 = (const float*)d_in[7];
    const float* b2 = (const float*)d_in[8];
    const float* w3 = (const float*)d_in[9];
    const float* b3 = (const float*)d_in[10];
    const float* w4 = (const float*)d_in[11];
    const float* b4 = (const float*)d_in[12];
    float* out = (float*)d_out;

    cudaFuncSetAttribute(mlp_fused, cudaFuncAttributeMaxDynamicSharedMemorySize, SMEM_TOTAL);

    prep_weights<<<KIN, 256>>>(w0, w1, w2, w3, w4);
    feat_prep   <<<(NBATCH * NH * NW * NCHAN + 255) / 256, 256>>>(feat);

    mlp_fused<<<NROWS / 128, 512, SMEM_TOTAL>>>(coord, cell, b0, b1, b2, b3, b4, out);
}

// round 12
// speedup vs baseline: 3.9173x; 1.5127x over previous
#include <cuda_runtime.h>
#include <cuda_bf16.h>
#include <math.h>
#include <cstdint>

// ---------------- problem constants ----------------
#define NBATCH 8
#define NCHAN  64
#define NH     48
#define NW     48
#define NQ     8192
#define BQ     (NBATCH * NQ)      // 65536 queries
#define NROWS  (4 * BQ)           // 262144 MLP rows (4 shifts)
#define NPIX   (NBATCH * NH * NW) // 18432 distinct pixels
#define KREAL  596
#define HID    256
#define OUTD   27

typedef __nv_bfloat16 bf16;

// ---------------- device globals (allocation-free rule) ----------------
__device__ bf16  g_Fh [NBATCH * NH * NW * NCHAN];   // feat NHWC hi plane (2.25 MB)
__device__ bf16  g_Fl [NBATCH * NH * NW * NCHAN];
__device__ float g_P  [(size_t)NPIX * HID];         // per-pixel patch@W0 (18.9 MB, L2-resident)
__device__ bf16  g_W0ph[HID * 576];                 // w0^T rows 0..575, K-permuted (k'=p*64+c)
__device__ bf16  g_W0pl[HID * 576];
__device__ bf16  g_WTh[HID * 32];                   // w0^T tail rows 576..607 (rel+cell+pad)
__device__ bf16  g_WTl[HID * 32];
__device__ bf16  g_W1h[HID * HID];
__device__ bf16  g_W1l[HID * HID];
__device__ bf16  g_W2h[HID * HID];
__device__ bf16  g_W2l[HID * HID];
__device__ bf16  g_W3h[HID * HID];
__device__ bf16  g_W3l[HID * HID];
__device__ float g_W4t[OUTD * 260];                 // w4^T, row-padded to 260 fp32

// ---------------- PTX helpers ----------------
__device__ __forceinline__ uint32_t smem_u32(const void* p) {
    uint32_t a;
    asm("{ .reg .u64 t; cvta.to.shared.u64 t, %1; cvt.u32.u64 %0, t; }" : "=r"(a) : "l"(p));
    return a;
}
__device__ __forceinline__ void cpa16(uint32_t s, const void* g) {
    asm volatile("cp.async.cg.shared.global [%0], [%1], 16;" :: "r"(s), "l"(g));
}
__device__ __forceinline__ void cpa16z(uint32_t s, const void* g, uint32_t n) {
    asm volatile("cp.async.cg.shared.global [%0], [%1], 16, %2;" :: "r"(s), "l"(g), "r"(n));
}
#define CP_COMMIT() asm volatile("cp.async.commit_group;" ::: "memory")
template<int N>
__device__ __forceinline__ void cp_wait() {
    asm volatile("cp.async.wait_group %0;" :: "n"(N) : "memory");
}
__device__ __forceinline__ void ldsm4(uint32_t (&r)[4], uint32_t addr) {
    asm volatile("ldmatrix.sync.aligned.m8n8.x4.shared.b16 {%0,%1,%2,%3}, [%4];"
        : "=r"(r[0]), "=r"(r[1]), "=r"(r[2]), "=r"(r[3]) : "r"(addr));
}
__device__ __forceinline__ void mma16816(float (&c)[4], const uint32_t (&a)[4],
                                         uint32_t b0, uint32_t b1) {
    asm volatile("mma.sync.aligned.m16n8k16.row.col.f32.bf16.bf16.f32 "
        "{%0,%1,%2,%3}, {%4,%5,%6,%7}, {%8,%9}, {%0,%1,%2,%3};"
        : "+f"(c[0]), "+f"(c[1]), "+f"(c[2]), "+f"(c[3])
        : "r"(a[0]), "r"(a[1]), "r"(a[2]), "r"(a[3]), "r"(b0), "r"(b1));
}
__device__ __forceinline__ void split_bf16(float v, bf16& h, bf16& l) {
    h = __float2bfloat16(v);
    l = __float2bfloat16(v - __bfloat162float(h));
}

// ---------------- smem layout: mlp_fused (one CTA/SM) ----------------
#define ASTRIDE  528
#define ABUF_LO  67584                 // lo plane offset inside A-buf
#define G_STAGE  20480                 // gather stage (Ah 10240 + Al 10240), overlays A-buf
#define OFF_BST  135168                // B stream: 2 stages x (Bh 20480 + Bl 20480)
#define BSTAGE   40960
#define OFF_W4   135168                // final phase: w4^T overlay (27 x 260 fp32)
#define OFF_HC   163264                // final phase: Hc (32 x 260 fp32)
#define OFF_BIAS 217088                // 256 f32
#define OFF_AREA 218112                // 128 f32
#define OFF_PIX  218624                // 128 i32
#define SMEM_TOTAL 219136

// ---------------- smem layout: p_gemm ----------------
#define PG_BST   40960                 // gather stages at 0 (2 x 20480), B at 40960 (2 x 40960)
#define PG_SMEM  122880

// ---------------- weight prep ----------------
__global__ void prep_weights(const float* __restrict__ w0, const float* __restrict__ w1,
                             const float* __restrict__ w2, const float* __restrict__ w3,
                             const float* __restrict__ w4)
{
    int idx = blockIdx.x * 256 + threadIdx.x;      // grid 608 -> up to 155648
    if (idx < HID * 576) {
        int n = idx / 576, kp = idx - n * 576;
        int p = kp >> 6, c = kp & 63;
        int ko = c * 9 + p;
        split_bf16(w0[ko * HID + n], g_W0ph[idx], g_W0pl[idx]);
    }
    if (idx < HID * 32) {
        int n = idx >> 5, j = idx & 31;
        float v = (j < 20) ? w0[(576 + j) * HID + n] : 0.0f;
        split_bf16(v, g_WTh[idx], g_WTl[idx]);
    }
    if (idx < HID * HID) {
        int n = idx >> 8, k = idx & 255;
        split_bf16(w1[k * HID + n], g_W1h[idx], g_W1l[idx]);
        split_bf16(w2[k * HID + n], g_W2h[idx], g_W2l[idx]);
        split_bf16(w3[k * HID + n], g_W3h[idx], g_W3l[idx]);
    }
    if (idx < OUTD * HID) {
        int o = idx >> 8, k = idx & 255;
        g_W4t[o * 260 + k] = w4[k * OUTD + o];
    }
}

// ---------------- feat -> NHWC bf16 hi/lo planes ----------------
__global__ void feat_prep(const float* __restrict__ feat)
{
    int idx = blockIdx.x * 256 + threadIdx.x;
    if (idx >= NBATCH * NH * NW * NCHAN) return;
    int t = idx;
    int c = t & 63; t >>= 6;
    int w = t % 48; t /= 48;
    int h = t % 48; int b = t / 48;
    float v = feat[(((size_t)b * 64 + c) * 48 + h) * 48 + w];
    split_bf16(v, g_Fh[idx], g_Fl[idx]);
}

// ---------------- coordinate helper ----------------
__device__ __forceinline__ void calc_rc(const float* cp, int s, int& row, int& col)
{
    const float SP  = (float)( 1.0 / 48.0 + 1e-6);
    const float SN  = (float)(-1.0 / 48.0 + 1e-6);
    const float CLO = (float)(-1.0 + 1e-6);
    const float CHI = (float)( 1.0 - 1e-6);
    float cx = cp[8] + ((s & 2) ? SP : SN);
    float cy = cp[9] + ((s & 1) ? SP : SN);
    cx = fminf(fmaxf(cx, CLO), CHI);
    cy = fminf(fmaxf(cy, CLO), CHI);
    row = (int)rintf((cx + 1.0f) * 24.0f - 0.5f);
    col = (int)rintf((cy + 1.0f) * 24.0f - 0.5f);
    row = min(max(row, 0), NH - 1);
    col = min(max(col, 0), NW - 1);
}

// ---------------- MMA step: 3-term bf16 split, warp tile 32x64 ----------------
#define MMA_STEP(AHB, ALB, AOFF, AKO, BHB, BLB, BKO)                                 \
    do {                                                                             \
        uint32_t ah[2][4], bh[4][4];                                                 \
        _Pragma("unroll")                                                            \
        for (int i = 0; i < 2; i++) ldsm4(ah[i], (AHB) + (AOFF)[i] + (AKO));         \
        _Pragma("unroll")                                                            \
        for (int j = 0; j < 4; j++) ldsm4(bh[j], (BHB) + boff[j] + (BKO));           \
        _Pragma("unroll")                                                            \
        for (int i = 0; i < 2; i++)                                                  \
            _Pragma("unroll")                                                        \
            for (int j = 0; j < 4; j++)                                              \
                _Pragma("unroll")                                                    \
                for (int h = 0; h < 2; h++)                                          \
                    mma16816(acc[i][j * 2 + h], ah[i], bh[j][2 * h], bh[j][2 * h + 1]); \
        uint32_t al[2][4];                                                           \
        _Pragma("unroll")                                                            \
        for (int i = 0; i < 2; i++) ldsm4(al[i], (ALB) + (AOFF)[i] + (AKO));         \
        _Pragma("unroll")                                                            \
        for (int i = 0; i < 2; i++)                                                  \
            _Pragma("unroll")                                                        \
            for (int j = 0; j < 4; j++)                                              \
                _Pragma("unroll")                                                    \
                for (int h = 0; h < 2; h++)                                          \
                    mma16816(acc[i][j * 2 + h], al[i], bh[j][2 * h], bh[j][2 * h + 1]); \
        uint32_t bl[4][4];                                                           \
        _Pragma("unroll")                                                            \
        for (int j = 0; j < 4; j++) ldsm4(bl[j], (BLB) + boff[j] + (BKO));           \
        _Pragma("unroll")                                                            \
        for (int i = 0; i < 2; i++)                                                  \
            _Pragma("unroll")                                                        \
            for (int j = 0; j < 4; j++)                                              \
                _Pragma("unroll")                                                    \
                for (int h = 0; h < 2; h++)                                          \
                    mma16816(acc[i][j * 2 + h], ah[i], bl[j][2 * h], bl[j][2 * h + 1]); \
    } while (0)

#define ZERO_ACC()                                                                   \
    _Pragma("unroll")                                                                \
    for (int i = 0; i < 2; i++)                                                      \
        _Pragma("unroll")                                                            \
        for (int j = 0; j < 8; j++)                                                  \
            _Pragma("unroll")                                                        \
            for (int r = 0; r < 4; r++) acc[i][j][r] = 0.0f;

#define FRAG_OFFSETS()                                                               \
    uint32_t aoff0[2], aoffA[2], boff[4];                                            \
    _Pragma("unroll")                                                                \
    for (int i = 0; i < 2; i++) {                                                    \
        int rb = wm * 32 + i * 16 + (lane & 15);                                     \
        aoff0[i] = (uint32_t)(rb * 80)      + ((lane >> 4) << 4);                    \
        aoffA[i] = (uint32_t)(rb * ASTRIDE) + ((lane >> 4) << 4);                    \
    }                                                                                \
    _Pragma("unroll")                                                                \
    for (int j = 0; j < 4; j++) {                                                    \
        int rb = wn * 64 + j * 16 + (lane & 7) + ((lane >> 4) << 3);                 \
        boff[j] = (uint32_t)(rb * 80) + (((lane >> 3) & 1) << 4);                    \
    }

// epilogue: relu(acc+bias), split hi/lo, write into smem A-buffer
#define EPI_TO_SMEM()                                                                \
    _Pragma("unroll")                                                                \
    for (int i = 0; i < 2; i++) {                                                    \
        const int r0 = wm * 32 + i * 16 + (lane >> 2);                               \
        _Pragma("unroll")                                                            \
        for (int jj = 0; jj < 8; jj++) {                                             \
            const int ncl = wn * 64 + jj * 8 + (lane & 3) * 2;                       \
            const float bz0 = biasS[ncl], bz1 = biasS[ncl + 1];                      \
            _Pragma("unroll")                                                        \
            for (int p = 0; p < 2; p++) {                                            \
                float v0 = fmaxf(acc[i][jj][2 * p + 0] + bz0, 0.0f);                 \
                float v1 = fmaxf(acc[i][jj][2 * p + 1] + bz1, 0.0f);                 \
                bf16 h0, l0, h1, l1;                                                 \
                split_bf16(v0, h0, l0);                                              \
                split_bf16(v1, h1, l1);                                              \
                const int row = r0 + p * 8;                                          \
                *(__nv_bfloat162*)(smem + row * ASTRIDE + ncl * 2)                   \
                    = __nv_bfloat162(h0, h1);                                        \
                *(__nv_bfloat162*)(smem + ABUF_LO + row * ASTRIDE + ncl * 2)         \
                    = __nv_bfloat162(l0, l1);                                        \
            }                                                                        \
        }                                                                            \
    }

// ---------------- p_gemm: P[pix] = unfold(feat)[pix] @ W0[:576]^T (fp32 out) ----
__global__ void __launch_bounds__(512, 1) p_gemm()
{
    extern __shared__ char smem[];
    const int tid  = threadIdx.x;
    const int lane = tid & 31;
    const int wid  = tid >> 5;
    const int wm   = wid & 3;
    const int wn   = wid >> 2;
    const int row0 = blockIdx.x * 128;
    const uint32_t sb = smem_u32(smem);

    // per-thread gather identity (4 threads per pixel row)
    const int cr = tid >> 2;
    const int sg = tid & 3;
    const int pix = row0 + cr;
    const int pb  = pix / 2304;
    const int prem = pix - pb * 2304;
    const int ph  = prem / 48;
    const int pw  = prem - ph * 48;

    uint32_t aoff0[2], boff[4];
    #pragma unroll
    for (int i = 0; i < 2; i++) {
        int rb = wm * 32 + i * 16 + (lane & 15);
        aoff0[i] = (uint32_t)(rb * 80) + ((lane >> 4) << 4);
    }
    #pragma unroll
    for (int j = 0; j < 4; j++) {
        int rb = wn * 64 + j * 16 + (lane & 7) + ((lane >> 4) << 3);
        boff[j] = (uint32_t)(rb * 80) + (((lane >> 3) & 1) << 4);
    }

    const int br  = tid >> 1;
    const int b2s = (tid & 1) << 1;

    auto load0 = [&](int c, int ps) {
        uint32_t bb = sb + PG_BST + (uint32_t)ps * BSTAGE;
        uint32_t bo = (uint32_t)(br * 80) + ((uint32_t)b2s << 4);
        const bf16* gbh = g_W0ph + (size_t)br * 576 + c * 32 + b2s * 8;
        const bf16* gbl = g_W0pl + (size_t)br * 576 + c * 32 + b2s * 8;
        cpa16(bb + bo,              gbh);
        cpa16(bb + bo + 16,         gbh + 8);
        cpa16(bb + 20480 + bo,      gbl);
        cpa16(bb + 20480 + bo + 16, gbl + 8);
        uint32_t ab = sb + (uint32_t)ps * G_STAGE;
        uint32_t ao = (uint32_t)(cr * 80) + ((uint32_t)sg << 4);
        int p  = c >> 1;
        int hh = ph + p / 3 - 1;
        int ww = pw + p % 3 - 1;
        uint32_t ok = (((unsigned)hh < 48u) && ((unsigned)ww < 48u)) ? 16u : 0u;
        int hc = min(max(hh, 0), 47), wc = min(max(ww, 0), 47);
        size_t gi = ((((size_t)pb * 48 + hc) * 48 + wc) << 6)
                  + ((c & 1) << 5) + (sg << 3);
        cpa16z(ab + ao,         g_Fh + gi, ok);
        cpa16z(ab + 10240 + ao, g_Fl + gi, ok);
    };

    float acc[2][8][4];
    ZERO_ACC();

    load0(0, 0);
    CP_COMMIT();
    for (int c = 0; c < 18; c++) {
        const int st = c & 1;
        if (c + 1 < 18) { load0(c + 1, st ^ 1); CP_COMMIT(); cp_wait<1>(); }
        else            { cp_wait<0>(); }
        __syncthreads();
        uint32_t ahb = sb + (uint32_t)st * G_STAGE;
        uint32_t alb = ahb + 10240;
        uint32_t bhb = sb + PG_BST + (uint32_t)st * BSTAGE;
        uint32_t blb = bhb + 20480;
        MMA_STEP(ahb, alb, aoff0, 0u,  bhb, blb, 0u);
        MMA_STEP(ahb, alb, aoff0, 32u, bhb, blb, 32u);
        __syncthreads();
    }

    // fp32 epilogue -> g_P
    #pragma unroll
    for (int i = 0; i < 2; i++) {
        const int r0 = wm * 32 + i * 16 + (lane >> 2);
        #pragma unroll
        for (int jj = 0; jj < 8; jj++) {
            const int ncl = wn * 64 + jj * 8 + (lane & 3) * 2;
            #pragma unroll
            for (int p = 0; p < 2; p++) {
                const int prow = row0 + r0 + p * 8;
                *(float2*)(g_P + (size_t)prow * HID + ncl)
                    = make_float2(acc[i][jj][2 * p + 0], acc[i][jj][2 * p + 1]);
            }
        }
    }
}

// ---------------- fused MLP: correction + layers 1-3 + blend + final GEMM --------
// Row order: grow = bq*4 + s  (all 4 shifts of a query adjacent -> CTA-local blend)
__global__ void __launch_bounds__(512, 1)
mlp_fused(const float* __restrict__ coord, const float* __restrict__ cell,
          const float* __restrict__ b0, const float* __restrict__ b1,
          const float* __restrict__ b2, const float* __restrict__ b3,
          const float* __restrict__ b4, float* __restrict__ out)
{
    extern __shared__ char smem[];
    const int tid  = threadIdx.x;
    const int lane = tid & 31;
    const int wid  = tid >> 5;
    const int wm   = wid & 3;        // M group (32 rows)
    const int wn   = wid >> 2;       // N group (64 cols)
    const int row0 = blockIdx.x * 128;
    const int bq0  = blockIdx.x * 32;

    float* biasS = (float*)(smem + OFF_BIAS);
    float* areaS = (float*)(smem + OFF_AREA);
    int*   pixS  = (int*)(smem + OFF_PIX);
    const uint32_t sb = smem_u32(smem);

    // ---- gather identity for this thread (4 threads per row) ----
    const int cr = tid >> 2;         // local row 0..127
    const int sg = tid & 3;          // segment 0..3
    const int grow = row0 + cr;
    const int gbq  = grow >> 2;
    const int gs   = grow & 3;
    const float* cpr = coord + (size_t)gbq * 18;
    int irow, icol;
    calc_rc(cpr, gs, irow, icol);
    const float qcr_r = (float)(2 * irow + 1) / 48.0f - 1.0f;
    const float qcc_r = (float)(2 * icol + 1) / 48.0f - 1.0f;

    // ---- per-row area + pixel index (1 thread per row) ----
    if (tid < 128) {
        int gr = row0 + tid;
        int bq = gr >> 2, s = gr & 3;
        int bb = bq >> 13;
        const float* cp = coord + (size_t)bq * 18;
        int r, c;
        calc_rc(cp, s, r, c);
        float qr = (float)(2 * r + 1) / 48.0f - 1.0f;
        float qc = (float)(2 * c + 1) / 48.0f - 1.0f;
        float ax = (cp[0] - qr) * 2304.0f;
        float ay = (cp[1] - qc);
        areaS[tid] = fabsf(ax * ay) + 1e-9f;
        pixS[tid]  = (bb * 48 + r) * 48 + c;
    }
    if (tid < 256) biasS[tid] = b0[tid];

    FRAG_OFFSETS();

    const int br  = tid >> 1;        // B row 0..255
    const int b2s = (tid & 1) << 1;

    auto loadB = [&](const bf16* Wh, const bf16* Wl, int c, int ps) {
        uint32_t bb = sb + OFF_BST + (uint32_t)ps * BSTAGE;
        uint32_t bo = (uint32_t)(br * 80) + ((uint32_t)b2s << 4);
        const bf16* gbh = Wh + (size_t)br * HID + c * 32 + b2s * 8;
        const bf16* gbl = Wl + (size_t)br * HID + c * 32 + b2s * 8;
        cpa16(bb + bo,              gbh);
        cpa16(bb + bo + 16,         gbh + 8);
        cpa16(bb + 20480 + bo,      gbl);
        cpa16(bb + 20480 + bo + 16, gbl + 8);
    };

    float acc[2][8][4];
    ZERO_ACC();

    // ================= layer 0 correction: K=32 (rel 18 + cell 2 + pad) ==========
    {
        // B = WT (stride 32)
        uint32_t bb = sb + OFF_BST;
        uint32_t bo = (uint32_t)(br * 80) + ((uint32_t)b2s << 4);
        const bf16* gbh = g_WTh + br * 32 + b2s * 8;
        const bf16* gbl = g_WTl + br * 32 + b2s * 8;
        cpa16(bb + bo,              gbh);
        cpa16(bb + bo + 16,         gbh + 8);
        cpa16(bb + 20480 + bo,      gbl);
        cpa16(bb + 20480 + bo + 16, gbl + 8);
        // A tail values -> gather stage 0 (hi/lo)
        bf16* dh = (bf16*)(smem + cr * 80);
        bf16* dl = dh + 5120;
        #pragma unroll
        for (int t = 0; t < 8; t++) {
            int l = sg * 8 + t;
            float v;
            if (l < 18)      { float cv = cpr[l]; v = (l & 1) ? (cv - qcc_r) : (cv - qcr_r) * 2304.0f; }
            else if (l < 20) { v = cell[(size_t)gbq * 2 + (l - 18)] * 48.0f; }
            else             { v = 0.0f; }
            bf16 h, lo;
            split_bf16(v, h, lo);
            dh[l] = h; dl[l] = lo;
        }
        CP_COMMIT();
        cp_wait<0>();
        __syncthreads();
        uint32_t bhb = sb + OFF_BST;
        uint32_t blb = bhb + 20480;
        MMA_STEP(sb, sb + 10240, aoff0, 0u,  bhb, blb, 0u);
        MMA_STEP(sb, sb + 10240, aoff0, 32u, bhb, blb, 32u);
        __syncthreads();
    }

    // ---- epilogue 0: acc + P[pix] + b0, relu, split -> A-buf ----
    #pragma unroll
    for (int i = 0; i < 2; i++) {
        const int r0 = wm * 32 + i * 16 + (lane >> 2);
        const int px0 = pixS[r0];
        const int px1 = pixS[r0 + 8];
        #pragma unroll
        for (int jj = 0; jj < 8; jj++) {
            const int ncl = wn * 64 + jj * 8 + (lane & 3) * 2;
            const float bz0 = biasS[ncl], bz1 = biasS[ncl + 1];
            #pragma unroll
            for (int p = 0; p < 2; p++) {
                const int px = p ? px1 : px0;
                float2 pv = *(const float2*)(g_P + (size_t)px * HID + ncl);
                float v0 = fmaxf(acc[i][jj][2 * p + 0] + pv.x + bz0, 0.0f);
                float v1 = fmaxf(acc[i][jj][2 * p + 1] + pv.y + bz1, 0.0f);
                bf16 h0, l0, h1, l1;
                split_bf16(v0, h0, l0);
                split_bf16(v1, h1, l1);
                const int row = r0 + p * 8;
                *(__nv_bfloat162*)(smem + row * ASTRIDE + ncl * 2)
                    = __nv_bfloat162(h0, h1);
                *(__nv_bfloat162*)(smem + ABUF_LO + row * ASTRIDE + ncl * 2)
                    = __nv_bfloat162(l0, l1);
            }
        }
    }
    __syncthreads();

    // ================= layers 1-3: A resident in smem =================
    const bf16* WH[3] = { g_W1h, g_W2h, g_W3h };
    const bf16* WL[3] = { g_W1l, g_W2l, g_W3l };
    const float* BB[3] = { b1, b2, b3 };

    for (int L = 0; L < 3; L++) {
        if (tid < 256) biasS[tid] = BB[L][tid];
        ZERO_ACC();
        loadB(WH[L], WL[L], 0, 0);
        CP_COMMIT();
        for (int c = 0; c < 8; c++) {
            const int st = c & 1;
            if (c + 1 < 8) { loadB(WH[L], WL[L], c + 1, st ^ 1); CP_COMMIT(); cp_wait<1>(); }
            else           { cp_wait<0>(); }
            __syncthreads();
            uint32_t ahb = sb;
            uint32_t alb = sb + ABUF_LO;
            uint32_t bhb = sb + OFF_BST + (uint32_t)st * BSTAGE;
            uint32_t blb = bhb + 20480;
            const uint32_t ako = (uint32_t)(c << 6);
            MMA_STEP(ahb, alb, aoffA, ako,       bhb, blb, 0u);
            MMA_STEP(ahb, alb, aoffA, ako + 32u, bhb, blb, 32u);
            __syncthreads();
        }
        EPI_TO_SMEM();
        __syncthreads();
    }

    // ================= stage w4^T into the dead B-stream region =================
    float* w4S = (float*)(smem + OFF_W4);
    float* hcS = (float*)(smem + OFF_HC);
    for (int i = tid; i < OUTD * HID; i += 512) {
        int o = i >> 8, k = i & 255;
        w4S[o * 260 + k] = g_W4t[o * 260 + k];
    }

    // ================= blend across shifts -> smem Hc (fp32) =================
    for (int idx = tid; idx < 32 * HID; idx += 512) {
        const int q = idx >> 8, k = idx & 255;
        float a0 = areaS[q * 4 + 0];
        float a1 = areaS[q * 4 + 1];
        float a2 = areaS[q * 4 + 2];
        float a3 = areaS[q * 4 + 3];
        float inv = 1.0f / (a0 + a1 + a2 + a3);
        float hc = 0.0f;
        #pragma unroll
        for (int s = 0; s < 4; s++) {
            const int row = q * 4 + s;
            float h = __bfloat162float(*(const bf16*)(smem + row * ASTRIDE + k * 2))
                    + __bfloat162float(*(const bf16*)(smem + ABUF_LO + row * ASTRIDE + k * 2));
            float w = (s == 0) ? a3 : (s == 1) ? a2 : (s == 2) ? a1 : a0;
            hc += h * w;
        }
        hcS[q * 260 + k] = hc * inv;
    }
    __syncthreads();

    // ================= final 256 -> 27 GEMM: warp q, lane o =================
    #pragma unroll
    for (int rep = 0; rep < 2; rep++) {
        const int q = wid * 2 + rep;
        if (lane < OUTD) {
            const float* hq = hcS + q * 260;
            const float* wo = w4S + lane * 260;
            float s = 0.0f;
            #pragma unroll 4
            for (int k = 0; k < HID; k += 4) {
                float4 h4 = *(const float4*)(hq + k);   // warp-broadcast
                float4 w4v = *(const float4*)(wo + k);
                s += h4.x * w4v.x + h4.y * w4v.y + h4.z * w4v.z + h4.w * w4v.w;
            }
            out[(size_t)(bq0 + q) * OUTD + lane] = s + __ldg(&b4[lane]);
        }
    }
}

// ---------------- launch ----------------
extern "C" void kernel_launch(void* const* d_in, const int* in_sizes, int n_in,
                              void* d_out, int out_size)
{
    const float* feat  = (const float*)d_in[0];
    const float* coord = (const float*)d_in[1];
    const float* cell  = (const float*)d_in[2];
    const float* w0 = (const float*)d_in[3];
    const float* b0 = (const float*)d_in[4];
    const float* w1 = (const float*)d_in[5];
    const float* b1 = (const float*)d_in[6];
    const float* w2 = (const float*)d_in[7];
    const float* b2 = (const float*)d_in[8];
    const float* w3 = (const float*)d_in[9];
    const float* b3 = (const float*)d_in[10];
    const float* w4 = (const float*)d_in[11];
    const float* b4 = (const float*)d_in[12];
    float* out = (float*)d_out;

    cudaFuncSetAttribute(p_gemm,    cudaFuncAttributeMaxDynamicSharedMemorySize, PG_SMEM);
    cudaFuncSetAttribute(mlp_fused, cudaFuncAttributeMaxDynamicSharedMemorySize, SMEM_TOTAL);

    prep_weights<<<608, 256>>>(w0, w1, w2, w3, w4);
    feat_prep   <<<(NBATCH * NH * NW * NCHAN + 255) / 256, 256>>>(feat);

    p_gemm<<<NPIX / 128, 512, PG_SMEM>>>();                              // 144 CTAs, ~1 wave

    mlp_fused<<<NROWS / 128, 512, SMEM_TOTAL>>>(coord, cell, b0, b1, b2, b3, b4, out);
}